// round 9
// baseline (speedup 1.0000x reference)
#include <cuda_runtime.h>
#include <cuda_bf16.h>
#include <cstdint>

#define BB      20000
#define NN      20
#define NODE_D  172
#define EDGE_D  172
#define TIME_D  100
#define QD      272          // NODE_D + TIME_D
#define KD      444          // NODE_D + EDGE_D + TIME_D
#define NH      2
#define HD      136
#define QT      (NH*KD)      // 888
#define ATTN_SCALE 0.08574929257125442f   // 136^-0.5
#define LN_EPS  1e-5f

// GEMM geometry (K-chunk = 32 bf16)
#define KPAD1   288          // GEMM1 K (272 -> 9 chunks)
#define NPAD1   960          // GEMM1 N (888 -> 10 tiles of 96)
#define KPAD2   896          // GEMM2 K (888 -> 28 chunks)
#define NPAD2   288          // GEMM2 N (272 -> 3 tiles of 96)
#define NCHUNK1 9
#define NCHUNK2 28
#define RSTR    40           // smem row stride in bf16 (80 B)

// ---------------- scratch -----------------------------------------------------
__device__ __align__(16) __nv_bfloat16 g_qin_hi[(size_t)BB * KPAD1];
__device__ __align__(16) __nv_bfloat16 g_qin_lo[(size_t)BB * KPAD1];
__device__ __align__(16) __nv_bfloat16 g_Mhi[NPAD1 * KPAD1];
__device__ __align__(16) __nv_bfloat16 g_Mlo[NPAD1 * KPAD1];
__device__ __align__(16) __nv_bfloat16 g_Rvhi[NPAD2 * KPAD2];
__device__ __align__(16) __nv_bfloat16 g_Rvlo[NPAD2 * KPAD2];
__device__ __align__(16) float         g_qt[(size_t)BB * NPAD1];
__device__ __align__(16) __nv_bfloat16 g_cxh[(size_t)BB * KPAD2];
__device__ __align__(16) __nv_bfloat16 g_cxl[(size_t)BB * KPAD2];
__device__ __align__(16) float         g_x[(size_t)BB * QD];

// ---------------- helpers -----------------------------------------------------
__device__ __forceinline__ uint32_t smem_u32(const void* p) {
    uint32_t a;
    asm("{ .reg .u64 t; cvta.to.shared.u64 t, %1; cvt.u32.u64 %0, t; }" : "=r"(a) : "l"(p));
    return a;
}
__device__ __forceinline__ void cp16(uint32_t dst, const void* src, bool v) {
    int sz = v ? 16 : 0;
    asm volatile("cp.async.cg.shared.global [%0], [%1], 16, %2;"
                 :: "r"(dst), "l"(src), "r"(sz));
}
#define CP_COMMIT() asm volatile("cp.async.commit_group;" ::: "memory")
#define CP_WAIT(n)  asm volatile("cp.async.wait_group %0;" :: "n"(n) : "memory")

#define LDM_X4(r, a) \
    asm volatile("ldmatrix.sync.aligned.m8n8.x4.shared.b16 {%0,%1,%2,%3}, [%4];" \
                 : "=r"((r)[0]), "=r"((r)[1]), "=r"((r)[2]), "=r"((r)[3]) : "r"(a))

__device__ __forceinline__ void mma_bf16(float* c, const uint32_t a[4],
                                         uint32_t b0, uint32_t b1) {
    asm volatile(
        "mma.sync.aligned.m16n8k16.row.col.f32.bf16.bf16.f32 "
        "{%0,%1,%2,%3}, {%4,%5,%6,%7}, {%8,%9}, {%0,%1,%2,%3};"
        : "+f"(c[0]), "+f"(c[1]), "+f"(c[2]), "+f"(c[3])
        : "r"(a[0]), "r"(a[1]), "r"(a[2]), "r"(a[3]), "r"(b0), "r"(b1));
}

__device__ __forceinline__ void split_bf16(float x, __nv_bfloat16& h, __nv_bfloat16& l) {
    h = __float2bfloat16(x);
    l = __float2bfloat16(x - __bfloat162float(h));
}

// ---------------- prep: qin = concat(nodef, ntime) -> hi/lo bf16 [B, 288] -----
__global__ void k_prep_qin(const float* __restrict__ nodef, const float* __restrict__ ntime)
{
    int i = blockIdx.x * blockDim.x + threadIdx.x;
    if (i >= BB * KPAD1) return;
    int r = i / KPAD1, c = i % KPAD1;
    float x = 0.f;
    if (c < NODE_D)   x = nodef[(size_t)r * NODE_D + c];
    else if (c < QD)  x = ntime[(size_t)r * TIME_D + (c - NODE_D)];
    __nv_bfloat16 h, l; split_bf16(x, h, l);
    g_qin_hi[i] = h; g_qin_lo[i] = l;
}

// ---------------- fold M = Wk^T Wq per head -> hi/lo [960, 288] ---------------
__global__ void k_fold_M(const float* __restrict__ Wq, const float* __restrict__ Wk)
{
    int tid = blockIdx.x * blockDim.x + threadIdx.x;
    if (tid >= NPAD1 * KPAD1) return;
    int c = tid % KPAD1;
    int o = tid / KPAD1;
    float acc = 0.f;
    if (o < QT && c < QD) {
        int h = o / KD, j = o % KD;
        const float* wk = Wk + (size_t)(h * HD) * KD + j;
        const float* wq = Wq + (size_t)(h * HD) * QD + c;
#pragma unroll 8
        for (int d = 0; d < HD; ++d)
            acc += wk[(size_t)d * KD] * wq[(size_t)d * QD];
    }
    __nv_bfloat16 h16, l16; split_bf16(acc, h16, l16);
    g_Mhi[tid] = h16; g_Mlo[tid] = l16;
}

// ---------------- fold Rv = Wr Wv per head -> hi/lo [288, 896] ----------------
__global__ void k_fold_Rv(const float* __restrict__ Wr, const float* __restrict__ Wv)
{
    int tid = blockIdx.x * blockDim.x + threadIdx.x;
    if (tid >= NPAD2 * KPAD2) return;
    int p = tid % KPAD2;
    int o = tid / KPAD2;
    float acc = 0.f;
    if (o < QD && p < QT) {
        int h = p / KD, j = p % KD;
        const float* wr = Wr + (size_t)o * QD + h * HD;
        const float* wv = Wv + (size_t)(h * HD) * KD + j;
#pragma unroll 8
        for (int d = 0; d < HD; ++d)
            acc += wr[d] * wv[(size_t)d * KD];
    }
    __nv_bfloat16 h16, l16; split_bf16(acc, h16, l16);
    g_Rvhi[tid] = h16; g_Rvlo[tid] = l16;
}

// ---------------- bf16x3 HMMA GEMM --------------------------------------------
// Block tile 128 x 96, 8 warps (4 M x 2 N), warp tile 32 x 48, K-chunk 32.
// smem 71.7 KB -> 3 CTAs/SM (24 warps) for latency hiding.
template<int BN, int NCH, int KP, int OSTR, bool FUSE, int WHICH>
__global__ __launch_bounds__(256)
void k_gemm_mma(const float* __restrict__ nodef, const float* __restrict__ ntime,
                const float* __restrict__ br)
{
    const __nv_bfloat16* __restrict__ Ah = (WHICH == 1) ? g_qin_hi : g_cxh;
    const __nv_bfloat16* __restrict__ Al = (WHICH == 1) ? g_qin_lo : g_cxl;
    const __nv_bfloat16* __restrict__ Bh = (WHICH == 1) ? g_Mhi : g_Rvhi;
    const __nv_bfloat16* __restrict__ Bl = (WHICH == 1) ? g_Mlo : g_Rvlo;
    float* __restrict__ outp             = (WHICH == 1) ? g_qt : g_x;

    constexpr int WN   = BN / 2;
    constexpr int WNS  = WN / 8;
    constexpr int NG   = WN / 16;
    constexpr int OFF_AL = 128 * 2 * RSTR;
    constexpr int OFF_BH = 2 * OFF_AL;
    constexpr int OFF_BL = OFF_BH + BN * 2 * RSTR;
    constexpr int STRIDE = OFF_BL + BN * 2 * RSTR;

    extern __shared__ char sm[];
    const uint32_t S = smem_u32(sm);
    const int t = threadIdx.x, lane = t & 31, wid = t >> 5;
    const int warpM = wid & 3, warpN = wid >> 2;
    const int bm = blockIdx.x, bn = blockIdx.y;

    float acc[2][WNS][4];
#pragma unroll
    for (int i = 0; i < 2; i++)
#pragma unroll
        for (int j = 0; j < WNS; j++)
#pragma unroll
            for (int q = 0; q < 4; q++) acc[i][j][q] = 0.f;

    auto load_chunk = [&](int c, int b) {
        const uint32_t base = S + b * STRIDE;
        for (int i = t; i < 512; i += 256) {
            int row = i >> 2, seg = i & 3;
            int gr = bm * 128 + row;
            bool v = gr < BB;
            int grc = v ? gr : (BB - 1);
            size_t off = (size_t)grc * KP + c * 32 + seg * 8;
            cp16(base + row * 80 + seg * 16, Ah + off, v);
            cp16(base + OFF_AL + row * 80 + seg * 16, Al + off, v);
        }
        for (int i = t; i < BN * 4; i += 256) {
            int row = i >> 2, seg = i & 3;
            size_t off = (size_t)(bn * BN + row) * KP + c * 32 + seg * 8;
            cp16(base + OFF_BH + row * 80 + seg * 16, Bh + off, true);
            cp16(base + OFF_BL + row * 80 + seg * 16, Bl + off, true);
        }
        CP_COMMIT();
    };

    load_chunk(0, 0);

    for (int c = 0; c < NCH; c++) {
        if (c + 1 < NCH) { load_chunk(c + 1, (c + 1) & 1); CP_WAIT(1); }
        else             { CP_WAIT(0); }
        __syncthreads();

        const uint32_t base = S + (c & 1) * STRIDE;
        const uint32_t lrow = lane & 15;
        const uint32_t lcol = (lane >> 4) * 16;

#pragma unroll
        for (int kk = 0; kk < 2; kk++) {
            const uint32_t kb = kk * 32 + lcol;
            uint32_t a_hi[2][4], a_lo[2][4];
#pragma unroll
            for (int ms = 0; ms < 2; ms++) {
                uint32_t r0 = (warpM * 32 + ms * 16 + lrow) * 80 + kb;
                LDM_X4(a_hi[ms], base + r0);
                LDM_X4(a_lo[ms], base + OFF_AL + r0);
            }
#pragma unroll
            for (int ng = 0; ng < NG; ng++) {
                uint32_t bh[4], bl[4];
                uint32_t r0 = (warpN * WN + ng * 16 + lrow) * 80 + kb;
                LDM_X4(bh, base + OFF_BH + r0);
                LDM_X4(bl, base + OFF_BL + r0);
#pragma unroll
                for (int ms = 0; ms < 2; ms++) {
                    mma_bf16(acc[ms][2*ng],   a_hi[ms], bh[0], bh[2]);
                    mma_bf16(acc[ms][2*ng+1], a_hi[ms], bh[1], bh[3]);
                }
#pragma unroll
                for (int ms = 0; ms < 2; ms++) {
                    mma_bf16(acc[ms][2*ng],   a_hi[ms], bl[0], bl[2]);
                    mma_bf16(acc[ms][2*ng+1], a_hi[ms], bl[1], bl[3]);
                }
#pragma unroll
                for (int ms = 0; ms < 2; ms++) {
                    mma_bf16(acc[ms][2*ng],   a_lo[ms], bh[0], bh[2]);
                    mma_bf16(acc[ms][2*ng+1], a_lo[ms], bh[1], bh[3]);
                }
            }
        }
        __syncthreads();
    }

    const int g = lane >> 2, tq = lane & 3;
#pragma unroll
    for (int ms = 0; ms < 2; ms++) {
#pragma unroll
        for (int ns = 0; ns < WNS; ns++) {
            int row = bm * 128 + warpM * 32 + ms * 16 + g;
            int col = bn * BN + warpN * WN + ns * 8 + tq * 2;
#pragma unroll
            for (int half = 0; half < 2; half++) {
                int r = row + half * 8;
                if (r >= BB) continue;
                float v0 = acc[ms][ns][half * 2 + 0];
                float v1 = acc[ms][ns][half * 2 + 1];
                if (FUSE) {
                    if (col >= QD) continue;
                    float2 res;
                    if (col < NODE_D) res = *(const float2*)(nodef + (size_t)r * NODE_D + col);
                    else              res = *(const float2*)(ntime + (size_t)r * TIME_D + (col - NODE_D));
                    float2 bb = *(const float2*)(br + col);
                    v0 += bb.x + res.x;
                    v1 += bb.y + res.y;
                }
                *(float2*)(outp + (size_t)r * OSTR + col) = make_float2(v0, v1);
            }
        }
    }
}

// ---------------- K2: streaming attention, one CTA per root row (R6 config) ---
__global__ __launch_bounds__(320)
void k_attn(const float* __restrict__ nbr_node, const float* __restrict__ nbr_time,
            const float* __restrict__ nbr_edge, const int* __restrict__ masks,
            float* __restrict__ out)
{
    __shared__ __align__(16) float kv[NN * KD];   // 35520 B
    __shared__ __align__(16) float qts[QT];       // 3552 B
    __shared__ float sc[NH * NN];

    const int b = blockIdx.x;
    const int t = threadIdx.x;
    const int w = t >> 5, lane = t & 31;
    const uint32_t kvS  = smem_u32(kv);
    const uint32_t qtsS = smem_u32(qts);

    for (int i = t; i < NN * (NODE_D / 4); i += 320) {
        int n = i / (NODE_D / 4), j4 = i % (NODE_D / 4);
        cp16(kvS + (n * KD + j4 * 4) * 4,
             nbr_node + ((size_t)b * NN + n) * NODE_D + j4 * 4, true);
    }
    for (int i = t; i < NN * (EDGE_D / 4); i += 320) {
        int n = i / (EDGE_D / 4), j4 = i % (EDGE_D / 4);
        cp16(kvS + (n * KD + NODE_D + j4 * 4) * 4,
             nbr_edge + ((size_t)b * NN + n) * EDGE_D + j4 * 4, true);
    }
    for (int i = t; i < NN * (TIME_D / 4); i += 320) {
        int n = i / (TIME_D / 4), j4 = i % (TIME_D / 4);
        cp16(kvS + (n * KD + NODE_D + EDGE_D + j4 * 4) * 4,
             nbr_time + ((size_t)b * NN + n) * TIME_D + j4 * 4, true);
    }
    for (int i = t; i < QT / 4; i += 320)
        cp16(qtsS + i * 16, g_qt + (size_t)b * NPAD1 + i * 4, true);
    CP_COMMIT();
    CP_WAIT(0);
    __syncthreads();

    {
        const int n0 = 2 * w, n1 = 2 * w + 1;
        float a00 = 0.f, a01 = 0.f, a10 = 0.f, a11 = 0.f;
        for (int j = lane; j < KD; j += 32) {
            float q0 = qts[j], q1 = qts[KD + j];
            float k0 = kv[n0 * KD + j], k1 = kv[n1 * KD + j];
            a00 += q0 * k0; a01 += q0 * k1;
            a10 += q1 * k0; a11 += q1 * k1;
        }
#pragma unroll
        for (int o = 16; o; o >>= 1) {
            a00 += __shfl_xor_sync(0xffffffffu, a00, o);
            a01 += __shfl_xor_sync(0xffffffffu, a01, o);
            a10 += __shfl_xor_sync(0xffffffffu, a10, o);
            a11 += __shfl_xor_sync(0xffffffffu, a11, o);
        }
        if (lane == 0) {
            int m0 = masks[(size_t)b * NN + n0];
            int m1 = masks[(size_t)b * NN + n1];
            sc[n0]      = (m0 == 0) ? -1e10f : a00 * ATTN_SCALE;
            sc[n1]      = (m1 == 0) ? -1e10f : a01 * ATTN_SCALE;
            sc[NN + n0] = (m0 == 0) ? -1e10f : a10 * ATTN_SCALE;
            sc[NN + n1] = (m1 == 0) ? -1e10f : a11 * ATTN_SCALE;
        }
    }
    __syncthreads();

    if (w < NH) {
        const int h = w;
        float x = (lane < NN) ? sc[h * NN + lane] : -INFINITY;
        float m = x;
#pragma unroll
        for (int o = 16; o; o >>= 1) m = fmaxf(m, __shfl_xor_sync(0xffffffffu, m, o));
        float e = (lane < NN) ? __expf(x - m) : 0.f;
        float ssum = e;
#pragma unroll
        for (int o = 16; o; o >>= 1) ssum += __shfl_xor_sync(0xffffffffu, ssum, o);
        float a = e / ssum;
        if (lane < NN) {
            sc[h * NN + lane] = a;
            out[(size_t)BB * QD + ((size_t)b * NH + h) * NN + lane] = a;
        }
    }
    __syncthreads();

    for (int j = t; j < KD; j += 320) {
        float c0 = 0.f, c1 = 0.f;
#pragma unroll
        for (int n = 0; n < NN; ++n) {
            float kvv = kv[n * KD + j];
            c0 += sc[n] * kvv;
            c1 += sc[NN + n] * kvv;
        }
        __nv_bfloat16 h0 = __float2bfloat16(c0);
        __nv_bfloat16 h1 = __float2bfloat16(c1);
        size_t base = (size_t)b * KPAD2;
        g_cxh[base + j]      = h0;
        g_cxl[base + j]      = __float2bfloat16(c0 - __bfloat162float(h0));
        g_cxh[base + KD + j] = h1;
        g_cxl[base + KD + j] = __float2bfloat16(c1 - __bfloat162float(h1));
    }
    if (t < KPAD2 - QT) {
        g_cxh[(size_t)b * KPAD2 + QT + t] = __float2bfloat16(0.f);
        g_cxl[(size_t)b * KPAD2 + QT + t] = __float2bfloat16(0.f);
    }
}

// ---------------- LayerNorm, one warp per row ---------------------------------
__global__ __launch_bounds__(256)
void k_ln(const float* __restrict__ gamma, const float* __restrict__ beta,
          float* __restrict__ out)
{
    int gw   = (blockIdx.x * blockDim.x + threadIdx.x) >> 5;
    int lane = threadIdx.x & 31;
    if (gw >= BB) return;
    const float* x = g_x + (size_t)gw * QD;
    float s = 0.f, s2 = 0.f;
    for (int j = lane; j < QD; j += 32) { float v = x[j]; s += v; s2 += v * v; }
#pragma unroll
    for (int o = 16; o; o >>= 1) {
        s  += __shfl_xor_sync(0xffffffffu, s,  o);
        s2 += __shfl_xor_sync(0xffffffffu, s2, o);
    }
    float mu   = s * (1.f / QD);
    float var  = s2 * (1.f / QD) - mu * mu;
    float rstd = rsqrtf(var + LN_EPS);
    for (int j = lane; j < QD; j += 32)
        out[(size_t)gw * QD + j] = (x[j] - mu) * rstd * gamma[j] + beta[j];
}

// ---------------- launch ------------------------------------------------------
#define SMEM1 (2 * (2 * 128 * 2 * RSTR + 2 * 96 * 2 * RSTR))   // 71680
#define SMEM2 (2 * (2 * 128 * 2 * RSTR + 2 * 96 * 2 * RSTR))   // 71680

extern "C" void kernel_launch(void* const* d_in, const int* in_sizes, int n_in,
                              void* d_out, int out_size)
{
    const float* nodef    = (const float*)d_in[0];
    const float* ntime    = (const float*)d_in[1];
    const float* nbr_node = (const float*)d_in[2];
    const float* nbr_time = (const float*)d_in[3];
    const float* nbr_edge = (const float*)d_in[4];
    const int*   masks    = (const int*)  d_in[5];
    const float* Wq       = (const float*)d_in[6];
    const float* Wk       = (const float*)d_in[7];
    const float* Wv       = (const float*)d_in[8];
    const float* Wr       = (const float*)d_in[9];
    const float* br       = (const float*)d_in[10];
    const float* gamma    = (const float*)d_in[11];
    const float* beta     = (const float*)d_in[12];
    float* out = (float*)d_out;

    auto g1 = k_gemm_mma<96, NCHUNK1, KPAD1, NPAD1, false, 1>;
    auto g2 = k_gemm_mma<96, NCHUNK2, KPAD2, QD,    true,  2>;
    cudaFuncSetAttribute(g1, cudaFuncAttributeMaxDynamicSharedMemorySize, SMEM1);
    cudaFuncSetAttribute(g2, cudaFuncAttributeMaxDynamicSharedMemorySize, SMEM2);

    k_prep_qin<<<(BB * KPAD1 + 255) / 256, 256>>>(nodef, ntime);
    k_fold_M <<<(NPAD1 * KPAD1 + 255) / 256, 256>>>(Wq, Wk);
    k_fold_Rv<<<(NPAD2 * KPAD2 + 255) / 256, 256>>>(Wr, Wv);

    dim3 grid1((BB + 127) / 128, NPAD1 / 96);
    g1<<<grid1, 256, SMEM1>>>(nodef, ntime, br);

    k_attn<<<BB, 320>>>(nbr_node, nbr_time, nbr_edge, masks, out);

    dim3 grid2((BB + 127) / 128, NPAD2 / 96);
    g2<<<grid2, 256, SMEM2>>>(nodef, ntime, br);

    k_ln<<<(BB * 32 + 255) / 256, 256>>>(gamma, beta, out);
}

// round 10
// speedup vs baseline: 1.4906x; 1.4906x over previous
#include <cuda_runtime.h>
#include <cuda_bf16.h>
#include <cstdint>

#define BB      20000
#define NN      20
#define NODE_D  172
#define EDGE_D  172
#define TIME_D  100
#define QD      272          // NODE_D + TIME_D
#define KD      444          // NODE_D + EDGE_D + TIME_D
#define NH      2
#define HD      136
#define QT      (NH*KD)      // 888
#define ATTN_SCALE 0.08574929257125442f   // 136^-0.5
#define LN_EPS  1e-5f

// GEMM geometry (K-chunk = 32 bf16) — R7 config (known good)
#define KPAD1   288          // GEMM1 K (272 -> 9 chunks)
#define NPAD1   896          // GEMM1 N (888 -> 7 tiles of 128)
#define KPAD2   896          // GEMM2 K (888 -> 28 chunks)
#define NPAD2   288          // GEMM2 N (272 -> 3 tiles of 96)
#define NCHUNK1 9
#define NCHUNK2 28
#define RSTR    40           // smem row stride in bf16 (80 B)

// pipeline chunking
#define NCHK    4
#define RC      (BB / NCHK)  // 5000 rows per chunk

// ---------------- scratch -----------------------------------------------------
__device__ __align__(16) __nv_bfloat16 g_qin_hi[(size_t)BB * KPAD1];
__device__ __align__(16) __nv_bfloat16 g_qin_lo[(size_t)BB * KPAD1];
__device__ __align__(16) __nv_bfloat16 g_Mhi[NPAD1 * KPAD1];
__device__ __align__(16) __nv_bfloat16 g_Mlo[NPAD1 * KPAD1];
__device__ __align__(16) __nv_bfloat16 g_Rvhi[NPAD2 * KPAD2];
__device__ __align__(16) __nv_bfloat16 g_Rvlo[NPAD2 * KPAD2];
__device__ __align__(16) float         g_qt[(size_t)BB * NPAD1];
__device__ __align__(16) __nv_bfloat16 g_cxh[(size_t)BB * KPAD2];
__device__ __align__(16) __nv_bfloat16 g_cxl[(size_t)BB * KPAD2];
__device__ __align__(16) float         g_x[(size_t)BB * QD];

// ---------------- helpers -----------------------------------------------------
__device__ __forceinline__ uint32_t smem_u32(const void* p) {
    uint32_t a;
    asm("{ .reg .u64 t; cvta.to.shared.u64 t, %1; cvt.u32.u64 %0, t; }" : "=r"(a) : "l"(p));
    return a;
}
__device__ __forceinline__ void cp16(uint32_t dst, const void* src, bool v) {
    int sz = v ? 16 : 0;
    asm volatile("cp.async.cg.shared.global [%0], [%1], 16, %2;"
                 :: "r"(dst), "l"(src), "r"(sz));
}
#define CP_COMMIT() asm volatile("cp.async.commit_group;" ::: "memory")
#define CP_WAIT(n)  asm volatile("cp.async.wait_group %0;" :: "n"(n) : "memory")

#define LDM_X4(r, a) \
    asm volatile("ldmatrix.sync.aligned.m8n8.x4.shared.b16 {%0,%1,%2,%3}, [%4];" \
                 : "=r"((r)[0]), "=r"((r)[1]), "=r"((r)[2]), "=r"((r)[3]) : "r"(a))

__device__ __forceinline__ void mma_bf16(float* c, const uint32_t a[4],
                                         uint32_t b0, uint32_t b1) {
    asm volatile(
        "mma.sync.aligned.m16n8k16.row.col.f32.bf16.bf16.f32 "
        "{%0,%1,%2,%3}, {%4,%5,%6,%7}, {%8,%9}, {%0,%1,%2,%3};"
        : "+f"(c[0]), "+f"(c[1]), "+f"(c[2]), "+f"(c[3])
        : "r"(a[0]), "r"(a[1]), "r"(a[2]), "r"(a[3]), "r"(b0), "r"(b1));
}

__device__ __forceinline__ void split_bf16(float x, __nv_bfloat16& h, __nv_bfloat16& l) {
    h = __float2bfloat16(x);
    l = __float2bfloat16(x - __bfloat162float(h));
}

// ---------------- prep: qin = concat(nodef, ntime) -> hi/lo bf16 [B, 288] -----
__global__ void k_prep_qin(const float* __restrict__ nodef, const float* __restrict__ ntime)
{
    int i = blockIdx.x * blockDim.x + threadIdx.x;
    if (i >= BB * KPAD1) return;
    int r = i / KPAD1, c = i % KPAD1;
    float x = 0.f;
    if (c < NODE_D)   x = nodef[(size_t)r * NODE_D + c];
    else if (c < QD)  x = ntime[(size_t)r * TIME_D + (c - NODE_D)];
    __nv_bfloat16 h, l; split_bf16(x, h, l);
    g_qin_hi[i] = h; g_qin_lo[i] = l;
}

// ---------------- fold M = Wk^T Wq per head -> hi/lo [896, 288] ---------------
__global__ void k_fold_M(const float* __restrict__ Wq, const float* __restrict__ Wk)
{
    int tid = blockIdx.x * blockDim.x + threadIdx.x;
    if (tid >= NPAD1 * KPAD1) return;
    int c = tid % KPAD1;
    int o = tid / KPAD1;
    float acc = 0.f;
    if (o < QT && c < QD) {
        int h = o / KD, j = o % KD;
        const float* wk = Wk + (size_t)(h * HD) * KD + j;
        const float* wq = Wq + (size_t)(h * HD) * QD + c;
#pragma unroll 8
        for (int d = 0; d < HD; ++d)
            acc += wk[(size_t)d * KD] * wq[(size_t)d * QD];
    }
    __nv_bfloat16 h16, l16; split_bf16(acc, h16, l16);
    g_Mhi[tid] = h16; g_Mlo[tid] = l16;
}

// ---------------- fold Rv = Wr Wv per head -> hi/lo [288, 896] ----------------
__global__ void k_fold_Rv(const float* __restrict__ Wr, const float* __restrict__ Wv)
{
    int tid = blockIdx.x * blockDim.x + threadIdx.x;
    if (tid >= NPAD2 * KPAD2) return;
    int p = tid % KPAD2;
    int o = tid / KPAD2;
    float acc = 0.f;
    if (o < QD && p < QT) {
        int h = p / KD, j = p % KD;
        const float* wr = Wr + (size_t)o * QD + h * HD;
        const float* wv = Wv + (size_t)(h * HD) * KD + j;
#pragma unroll 8
        for (int d = 0; d < HD; ++d)
            acc += wr[d] * wv[(size_t)d * KD];
    }
    __nv_bfloat16 h16, l16; split_bf16(acc, h16, l16);
    g_Rvhi[tid] = h16; g_Rvlo[tid] = l16;
}

// ---------------- bf16x3 HMMA GEMM (R7 config, + row-chunk bounds) ------------
template<int BN, int NCH, int KP, int OSTR, bool FUSE, int WHICH>
__global__ __launch_bounds__(256)
void k_gemm_mma(const float* __restrict__ nodef, const float* __restrict__ ntime,
                const float* __restrict__ br, int rowBeg, int rowEnd)
{
    const __nv_bfloat16* __restrict__ Ah = (WHICH == 1) ? g_qin_hi : g_cxh;
    const __nv_bfloat16* __restrict__ Al = (WHICH == 1) ? g_qin_lo : g_cxl;
    const __nv_bfloat16* __restrict__ Bh = (WHICH == 1) ? g_Mhi : g_Rvhi;
    const __nv_bfloat16* __restrict__ Bl = (WHICH == 1) ? g_Mlo : g_Rvlo;
    float* __restrict__ outp             = (WHICH == 1) ? g_qt : g_x;

    constexpr int WN   = BN / 2;
    constexpr int WNS  = WN / 8;
    constexpr int NG   = WN / 16;
    constexpr int OFF_AL = 128 * 2 * RSTR;
    constexpr int OFF_BH = 2 * OFF_AL;
    constexpr int OFF_BL = OFF_BH + BN * 2 * RSTR;
    constexpr int STRIDE = OFF_BL + BN * 2 * RSTR;

    extern __shared__ char sm[];
    const uint32_t S = smem_u32(sm);
    const int t = threadIdx.x, lane = t & 31, wid = t >> 5;
    const int warpM = wid & 3, warpN = wid >> 2;
    const int bm = blockIdx.x, bn = blockIdx.y;

    float acc[2][WNS][4];
#pragma unroll
    for (int i = 0; i < 2; i++)
#pragma unroll
        for (int j = 0; j < WNS; j++)
#pragma unroll
            for (int q = 0; q < 4; q++) acc[i][j][q] = 0.f;

    auto load_chunk = [&](int c, int b) {
        const uint32_t base = S + b * STRIDE;
        for (int i = t; i < 512; i += 256) {
            int row = i >> 2, seg = i & 3;
            int gr = rowBeg + bm * 128 + row;
            bool v = gr < rowEnd;
            int grc = v ? gr : (rowEnd - 1);
            size_t off = (size_t)grc * KP + c * 32 + seg * 8;
            cp16(base + row * 80 + seg * 16, Ah + off, v);
            cp16(base + OFF_AL + row * 80 + seg * 16, Al + off, v);
        }
        for (int i = t; i < BN * 4; i += 256) {
            int row = i >> 2, seg = i & 3;
            size_t off = (size_t)(bn * BN + row) * KP + c * 32 + seg * 8;
            cp16(base + OFF_BH + row * 80 + seg * 16, Bh + off, true);
            cp16(base + OFF_BL + row * 80 + seg * 16, Bl + off, true);
        }
        CP_COMMIT();
    };

    load_chunk(0, 0);

    for (int c = 0; c < NCH; c++) {
        if (c + 1 < NCH) { load_chunk(c + 1, (c + 1) & 1); CP_WAIT(1); }
        else             { CP_WAIT(0); }
        __syncthreads();

        const uint32_t base = S + (c & 1) * STRIDE;
        const uint32_t lrow = lane & 15;
        const uint32_t lcol = (lane >> 4) * 16;

#pragma unroll
        for (int kk = 0; kk < 2; kk++) {
            const uint32_t kb = kk * 32 + lcol;
            uint32_t a_hi[2][4], a_lo[2][4];
#pragma unroll
            for (int ms = 0; ms < 2; ms++) {
                uint32_t r0 = (warpM * 32 + ms * 16 + lrow) * 80 + kb;
                LDM_X4(a_hi[ms], base + r0);
                LDM_X4(a_lo[ms], base + OFF_AL + r0);
            }
#pragma unroll
            for (int ng = 0; ng < NG; ng++) {
                uint32_t bh[4], bl[4];
                uint32_t r0 = (warpN * WN + ng * 16 + lrow) * 80 + kb;
                LDM_X4(bh, base + OFF_BH + r0);
                LDM_X4(bl, base + OFF_BL + r0);
#pragma unroll
                for (int ms = 0; ms < 2; ms++) {
                    mma_bf16(acc[ms][2*ng],   a_hi[ms], bh[0], bh[2]);
                    mma_bf16(acc[ms][2*ng+1], a_hi[ms], bh[1], bh[3]);
                }
#pragma unroll
                for (int ms = 0; ms < 2; ms++) {
                    mma_bf16(acc[ms][2*ng],   a_hi[ms], bl[0], bl[2]);
                    mma_bf16(acc[ms][2*ng+1], a_hi[ms], bl[1], bl[3]);
                }
#pragma unroll
                for (int ms = 0; ms < 2; ms++) {
                    mma_bf16(acc[ms][2*ng],   a_lo[ms], bh[0], bh[2]);
                    mma_bf16(acc[ms][2*ng+1], a_lo[ms], bh[1], bh[3]);
                }
            }
        }
        __syncthreads();
    }

    const int g = lane >> 2, tq = lane & 3;
#pragma unroll
    for (int ms = 0; ms < 2; ms++) {
#pragma unroll
        for (int ns = 0; ns < WNS; ns++) {
            int row = rowBeg + bm * 128 + warpM * 32 + ms * 16 + g;
            int col = bn * BN + warpN * WN + ns * 8 + tq * 2;
#pragma unroll
            for (int half = 0; half < 2; half++) {
                int r = row + half * 8;
                if (r >= rowEnd) continue;
                float v0 = acc[ms][ns][half * 2 + 0];
                float v1 = acc[ms][ns][half * 2 + 1];
                if (FUSE) {
                    if (col >= QD) continue;
                    float2 res;
                    if (col < NODE_D) res = *(const float2*)(nodef + (size_t)r * NODE_D + col);
                    else              res = *(const float2*)(ntime + (size_t)r * TIME_D + (col - NODE_D));
                    float2 bb = *(const float2*)(br + col);
                    v0 += bb.x + res.x;
                    v1 += bb.y + res.y;
                }
                *(float2*)(outp + (size_t)r * OSTR + col) = make_float2(v0, v1);
            }
        }
    }
}

// ---------------- K2: streaming attention, one CTA per root row (R6 config) ---
__global__ __launch_bounds__(320)
void k_attn(const float* __restrict__ nbr_node, const float* __restrict__ nbr_time,
            const float* __restrict__ nbr_edge, const int* __restrict__ masks,
            float* __restrict__ out, int rowBeg)
{
    __shared__ __align__(16) float kv[NN * KD];   // 35520 B
    __shared__ __align__(16) float qts[QT];       // 3552 B
    __shared__ float sc[NH * NN];

    const int b = rowBeg + blockIdx.x;
    const int t = threadIdx.x;
    const int w = t >> 5, lane = t & 31;
    const uint32_t kvS  = smem_u32(kv);
    const uint32_t qtsS = smem_u32(qts);

    for (int i = t; i < NN * (NODE_D / 4); i += 320) {
        int n = i / (NODE_D / 4), j4 = i % (NODE_D / 4);
        cp16(kvS + (n * KD + j4 * 4) * 4,
             nbr_node + ((size_t)b * NN + n) * NODE_D + j4 * 4, true);
    }
    for (int i = t; i < NN * (EDGE_D / 4); i += 320) {
        int n = i / (EDGE_D / 4), j4 = i % (EDGE_D / 4);
        cp16(kvS + (n * KD + NODE_D + j4 * 4) * 4,
             nbr_edge + ((size_t)b * NN + n) * EDGE_D + j4 * 4, true);
    }
    for (int i = t; i < NN * (TIME_D / 4); i += 320) {
        int n = i / (TIME_D / 4), j4 = i % (TIME_D / 4);
        cp16(kvS + (n * KD + NODE_D + EDGE_D + j4 * 4) * 4,
             nbr_time + ((size_t)b * NN + n) * TIME_D + j4 * 4, true);
    }
    for (int i = t; i < QT / 4; i += 320)
        cp16(qtsS + i * 16, g_qt + (size_t)b * NPAD1 + i * 4, true);
    CP_COMMIT();
    CP_WAIT(0);
    __syncthreads();

    {
        const int n0 = 2 * w, n1 = 2 * w + 1;
        float a00 = 0.f, a01 = 0.f, a10 = 0.f, a11 = 0.f;
        for (int j = lane; j < KD; j += 32) {
            float q0 = qts[j], q1 = qts[KD + j];
            float k0 = kv[n0 * KD + j], k1 = kv[n1 * KD + j];
            a00 += q0 * k0; a01 += q0 * k1;
            a10 += q1 * k0; a11 += q1 * k1;
        }
#pragma unroll
        for (int o = 16; o; o >>= 1) {
            a00 += __shfl_xor_sync(0xffffffffu, a00, o);
            a01 += __shfl_xor_sync(0xffffffffu, a01, o);
            a10 += __shfl_xor_sync(0xffffffffu, a10, o);
            a11 += __shfl_xor_sync(0xffffffffu, a11, o);
        }
        if (lane == 0) {
            int m0 = masks[(size_t)b * NN + n0];
            int m1 = masks[(size_t)b * NN + n1];
            sc[n0]      = (m0 == 0) ? -1e10f : a00 * ATTN_SCALE;
            sc[n1]      = (m1 == 0) ? -1e10f : a01 * ATTN_SCALE;
            sc[NN + n0] = (m0 == 0) ? -1e10f : a10 * ATTN_SCALE;
            sc[NN + n1] = (m1 == 0) ? -1e10f : a11 * ATTN_SCALE;
        }
    }
    __syncthreads();

    if (w < NH) {
        const int h = w;
        float x = (lane < NN) ? sc[h * NN + lane] : -INFINITY;
        float m = x;
#pragma unroll
        for (int o = 16; o; o >>= 1) m = fmaxf(m, __shfl_xor_sync(0xffffffffu, m, o));
        float e = (lane < NN) ? __expf(x - m) : 0.f;
        float ssum = e;
#pragma unroll
        for (int o = 16; o; o >>= 1) ssum += __shfl_xor_sync(0xffffffffu, ssum, o);
        float a = e / ssum;
        if (lane < NN) {
            sc[h * NN + lane] = a;
            out[(size_t)BB * QD + ((size_t)b * NH + h) * NN + lane] = a;
        }
    }
    __syncthreads();

    for (int j = t; j < KD; j += 320) {
        float c0 = 0.f, c1 = 0.f;
#pragma unroll
        for (int n = 0; n < NN; ++n) {
            float kvv = kv[n * KD + j];
            c0 += sc[n] * kvv;
            c1 += sc[NN + n] * kvv;
        }
        __nv_bfloat16 h0 = __float2bfloat16(c0);
        __nv_bfloat16 h1 = __float2bfloat16(c1);
        size_t base = (size_t)b * KPAD2;
        g_cxh[base + j]      = h0;
        g_cxl[base + j]      = __float2bfloat16(c0 - __bfloat162float(h0));
        g_cxh[base + KD + j] = h1;
        g_cxl[base + KD + j] = __float2bfloat16(c1 - __bfloat162float(h1));
    }
    if (t < KPAD2 - QT) {
        g_cxh[(size_t)b * KPAD2 + QT + t] = __float2bfloat16(0.f);
        g_cxl[(size_t)b * KPAD2 + QT + t] = __float2bfloat16(0.f);
    }
}

// ---------------- LayerNorm, one warp per row ---------------------------------
__global__ __launch_bounds__(256)
void k_ln(const float* __restrict__ gamma, const float* __restrict__ beta,
          float* __restrict__ out)
{
    int gw   = (blockIdx.x * blockDim.x + threadIdx.x) >> 5;
    int lane = threadIdx.x & 31;
    if (gw >= BB) return;
    const float* x = g_x + (size_t)gw * QD;
    float s = 0.f, s2 = 0.f;
    for (int j = lane; j < QD; j += 32) { float v = x[j]; s += v; s2 += v * v; }
#pragma unroll
    for (int o = 16; o; o >>= 1) {
        s  += __shfl_xor_sync(0xffffffffu, s,  o);
        s2 += __shfl_xor_sync(0xffffffffu, s2, o);
    }
    float mu   = s * (1.f / QD);
    float var  = s2 * (1.f / QD) - mu * mu;
    float rstd = rsqrtf(var + LN_EPS);
    for (int j = lane; j < QD; j += 32)
        out[(size_t)gw * QD + j] = (x[j] - mu) * rstd * gamma[j] + beta[j];
}

// ---------------- streams / events (created once at load, outside capture) ----
struct PipeRes {
    cudaStream_t s1, s2, s3;
    cudaEvent_t root, e1[NCHK], e2[NCHK], e3[NCHK];
    PipeRes() {
        cudaStreamCreateWithFlags(&s1, cudaStreamNonBlocking);
        cudaStreamCreateWithFlags(&s2, cudaStreamNonBlocking);
        cudaStreamCreateWithFlags(&s3, cudaStreamNonBlocking);
        cudaEventCreateWithFlags(&root, cudaEventDisableTiming);
        for (int i = 0; i < NCHK; i++) {
            cudaEventCreateWithFlags(&e1[i], cudaEventDisableTiming);
            cudaEventCreateWithFlags(&e2[i], cudaEventDisableTiming);
            cudaEventCreateWithFlags(&e3[i], cudaEventDisableTiming);
        }
    }
};
static PipeRes g_pipe;

// ---------------- launch ------------------------------------------------------
#define SMEM1 (2 * (4 * 128 * 2 * RSTR))                       // 81920
#define SMEM2 (2 * (2 * 128 * 2 * RSTR + 2 * 96 * 2 * RSTR))   // 71680

extern "C" void kernel_launch(void* const* d_in, const int* in_sizes, int n_in,
                              void* d_out, int out_size)
{
    const float* nodef    = (const float*)d_in[0];
    const float* ntime    = (const float*)d_in[1];
    const float* nbr_node = (const float*)d_in[2];
    const float* nbr_time = (const float*)d_in[3];
    const float* nbr_edge = (const float*)d_in[4];
    const int*   masks    = (const int*)  d_in[5];
    const float* Wq       = (const float*)d_in[6];
    const float* Wk       = (const float*)d_in[7];
    const float* Wv       = (const float*)d_in[8];
    const float* Wr       = (const float*)d_in[9];
    const float* br       = (const float*)d_in[10];
    const float* gamma    = (const float*)d_in[11];
    const float* beta     = (const float*)d_in[12];
    float* out = (float*)d_out;

    auto g1 = k_gemm_mma<128, NCHUNK1, KPAD1, NPAD1, false, 1>;
    auto g2 = k_gemm_mma<96,  NCHUNK2, KPAD2, QD,    true,  2>;
    cudaFuncSetAttribute(g1, cudaFuncAttributeMaxDynamicSharedMemorySize, SMEM1);
    cudaFuncSetAttribute(g2, cudaFuncAttributeMaxDynamicSharedMemorySize, SMEM2);

    // serial prefix on the launch stream
    k_prep_qin<<<(BB * KPAD1 + 255) / 256, 256>>>(nodef, ntime);
    k_fold_M <<<(NPAD1 * KPAD1 + 255) / 256, 256>>>(Wq, Wk);
    k_fold_Rv<<<(NPAD2 * KPAD2 + 255) / 256, 256>>>(Wr, Wv);

    // fork
    cudaEventRecord(g_pipe.root, 0);
    cudaStreamWaitEvent(g_pipe.s1, g_pipe.root, 0);
    cudaStreamWaitEvent(g_pipe.s2, g_pipe.root, 0);
    cudaStreamWaitEvent(g_pipe.s3, g_pipe.root, 0);

    const int gm = (RC + 127) / 128;   // 40 row-blocks per chunk
    for (int c = 0; c < NCHK; c++) {
        const int rb = c * RC;
        const int re = rb + RC;

        // GEMM1 chunk on s1
        dim3 grid1(gm, NPAD1 / 128);
        g1<<<grid1, 256, SMEM1, g_pipe.s1>>>(nodef, ntime, br, rb, re);
        cudaEventRecord(g_pipe.e1[c], g_pipe.s1);

        // attn chunk on s2 (after its GEMM1 chunk)
        cudaStreamWaitEvent(g_pipe.s2, g_pipe.e1[c], 0);
        k_attn<<<RC, 320, 0, g_pipe.s2>>>(nbr_node, nbr_time, nbr_edge, masks, out, rb);
        cudaEventRecord(g_pipe.e2[c], g_pipe.s2);

        // GEMM2 chunk on s3 (after its attn chunk)
        cudaStreamWaitEvent(g_pipe.s3, g_pipe.e2[c], 0);
        dim3 grid2(gm, NPAD2 / 96);
        g2<<<grid2, 256, SMEM2, g_pipe.s3>>>(nodef, ntime, br, rb, re);
        cudaEventRecord(g_pipe.e3[c], g_pipe.s3);
    }

    // join back to the launch stream, then LN
    for (int c = 0; c < NCHK; c++)
        cudaStreamWaitEvent(0, g_pipe.e3[c], 0);
    k_ln<<<(BB * 32 + 255) / 256, 256>>>(gamma, beta, out);
}

// round 11
// speedup vs baseline: 1.5406x; 1.0336x over previous
#include <cuda_runtime.h>
#include <cuda_bf16.h>
#include <cstdint>

#define BB      20000
#define NN      20
#define NODE_D  172
#define EDGE_D  172
#define TIME_D  100
#define QD      272          // NODE_D + TIME_D
#define KD      444          // NODE_D + EDGE_D + TIME_D
#define NH      2
#define HD      136
#define QT      (NH*KD)      // 888
#define ATTN_SCALE 0.08574929257125442f   // 136^-0.5
#define LN_EPS  1e-5f

// GEMM geometry (K-chunk = 32 bf16)
#define KPAD1   288          // GEMM1 K (272 -> 9 chunks)
#define NPAD1   896          // GEMM1 N (888 -> 7 tiles of 128)
#define KPAD2   896          // GEMM2 K (888 -> 28 chunks)
#define NPAD2   288          // GEMM2 N (272 -> 3 tiles of 96)
#define NCHUNK1 9
#define NCHUNK2 28
#define RSTR    40           // smem row stride in bf16 (80 B)

// ---------------- scratch -----------------------------------------------------
__device__ __align__(16) __nv_bfloat16 g_qin_hi[(size_t)BB * KPAD1];
__device__ __align__(16) __nv_bfloat16 g_qin_lo[(size_t)BB * KPAD1];
__device__ __align__(16) __nv_bfloat16 g_Mhi[NPAD1 * KPAD1];
__device__ __align__(16) __nv_bfloat16 g_Mlo[NPAD1 * KPAD1];
__device__ __align__(16) __nv_bfloat16 g_Rvhi[NPAD2 * KPAD2];
__device__ __align__(16) __nv_bfloat16 g_Rvlo[NPAD2 * KPAD2];
__device__ __align__(16) float         g_qt[(size_t)BB * NPAD1];
__device__ __align__(16) __nv_bfloat16 g_cxh[(size_t)BB * KPAD2];
__device__ __align__(16) __nv_bfloat16 g_cxl[(size_t)BB * KPAD2];
__device__ __align__(16) float         g_x[(size_t)BB * QD];

// ---------------- helpers -----------------------------------------------------
__device__ __forceinline__ uint32_t smem_u32(const void* p) {
    uint32_t a;
    asm("{ .reg .u64 t; cvta.to.shared.u64 t, %1; cvt.u32.u64 %0, t; }" : "=r"(a) : "l"(p));
    return a;
}
__device__ __forceinline__ void cp16(uint32_t dst, const void* src, bool v) {
    int sz = v ? 16 : 0;
    asm volatile("cp.async.cg.shared.global [%0], [%1], 16, %2;"
                 :: "r"(dst), "l"(src), "r"(sz));
}
#define CP_COMMIT() asm volatile("cp.async.commit_group;" ::: "memory")
#define CP_WAIT(n)  asm volatile("cp.async.wait_group %0;" :: "n"(n) : "memory")

#define LDM_X4(r, a) \
    asm volatile("ldmatrix.sync.aligned.m8n8.x4.shared.b16 {%0,%1,%2,%3}, [%4];" \
                 : "=r"((r)[0]), "=r"((r)[1]), "=r"((r)[2]), "=r"((r)[3]) : "r"(a))

__device__ __forceinline__ void mma_bf16(float* c, const uint32_t a[4],
                                         uint32_t b0, uint32_t b1) {
    asm volatile(
        "mma.sync.aligned.m16n8k16.row.col.f32.bf16.bf16.f32 "
        "{%0,%1,%2,%3}, {%4,%5,%6,%7}, {%8,%9}, {%0,%1,%2,%3};"
        : "+f"(c[0]), "+f"(c[1]), "+f"(c[2]), "+f"(c[3])
        : "r"(a[0]), "r"(a[1]), "r"(a[2]), "r"(a[3]), "r"(b0), "r"(b1));
}

__device__ __forceinline__ void split_bf16(float x, __nv_bfloat16& h, __nv_bfloat16& l) {
    h = __float2bfloat16(x);
    l = __float2bfloat16(x - __bfloat162float(h));
}

// ---------------- prep: qin = concat(nodef, ntime) -> hi/lo bf16 [B, 288] -----
__global__ void k_prep_qin(const float* __restrict__ nodef, const float* __restrict__ ntime)
{
    int i = blockIdx.x * blockDim.x + threadIdx.x;
    if (i >= BB * KPAD1) return;
    int r = i / KPAD1, c = i % KPAD1;
    float x = 0.f;
    if (c < NODE_D)   x = nodef[(size_t)r * NODE_D + c];
    else if (c < QD)  x = ntime[(size_t)r * TIME_D + (c - NODE_D)];
    __nv_bfloat16 h, l; split_bf16(x, h, l);
    g_qin_hi[i] = h; g_qin_lo[i] = l;
}

// ---------------- fold M = Wk^T Wq per head -> hi/lo [896, 288] ---------------
__global__ void k_fold_M(const float* __restrict__ Wq, const float* __restrict__ Wk)
{
    int tid = blockIdx.x * blockDim.x + threadIdx.x;
    if (tid >= NPAD1 * KPAD1) return;
    int c = tid % KPAD1;
    int o = tid / KPAD1;
    float acc = 0.f;
    if (o < QT && c < QD) {
        int h = o / KD, j = o % KD;
        const float* wk = Wk + (size_t)(h * HD) * KD + j;
        const float* wq = Wq + (size_t)(h * HD) * QD + c;
#pragma unroll 8
        for (int d = 0; d < HD; ++d)
            acc += wk[(size_t)d * KD] * wq[(size_t)d * QD];
    }
    __nv_bfloat16 h16, l16; split_bf16(acc, h16, l16);
    g_Mhi[tid] = h16; g_Mlo[tid] = l16;
}

// ---------------- fold Rv = Wr Wv per head -> hi/lo [288, 896] ----------------
__global__ void k_fold_Rv(const float* __restrict__ Wr, const float* __restrict__ Wv)
{
    int tid = blockIdx.x * blockDim.x + threadIdx.x;
    if (tid >= NPAD2 * KPAD2) return;
    int p = tid % KPAD2;
    int o = tid / KPAD2;
    float acc = 0.f;
    if (o < QD && p < QT) {
        int h = p / KD, j = p % KD;
        const float* wr = Wr + (size_t)o * QD + h * HD;
        const float* wv = Wv + (size_t)(h * HD) * KD + j;
#pragma unroll 8
        for (int d = 0; d < HD; ++d)
            acc += wr[d] * wv[(size_t)d * KD];
    }
    __nv_bfloat16 h16, l16; split_bf16(acc, h16, l16);
    g_Rvhi[tid] = h16; g_Rvlo[tid] = l16;
}

// ---------------- bf16x3 HMMA GEMM --------------------------------------------
// STAGES=2: classic double buffer (2 barriers/chunk).
// STAGES=3: triple buffer, ONE barrier per chunk (wait+sync at loop top both
//           publishes chunk c and retires buffer (c+2)%3's readers).
template<int BN, int NCH, int KP, int OSTR, bool FUSE, int WHICH, int STAGES>
__global__ __launch_bounds__(256)
void k_gemm_mma(const float* __restrict__ nodef, const float* __restrict__ ntime,
                const float* __restrict__ br)
{
    const __nv_bfloat16* __restrict__ Ah = (WHICH == 1) ? g_qin_hi : g_cxh;
    const __nv_bfloat16* __restrict__ Al = (WHICH == 1) ? g_qin_lo : g_cxl;
    const __nv_bfloat16* __restrict__ Bh = (WHICH == 1) ? g_Mhi : g_Rvhi;
    const __nv_bfloat16* __restrict__ Bl = (WHICH == 1) ? g_Mlo : g_Rvlo;
    float* __restrict__ outp             = (WHICH == 1) ? g_qt : g_x;

    constexpr int WN   = BN / 2;
    constexpr int WNS  = WN / 8;
    constexpr int NG   = WN / 16;
    constexpr int OFF_AL = 128 * 2 * RSTR;
    constexpr int OFF_BH = 2 * OFF_AL;
    constexpr int OFF_BL = OFF_BH + BN * 2 * RSTR;
    constexpr int STRIDE = OFF_BL + BN * 2 * RSTR;

    extern __shared__ char sm[];
    const uint32_t S = smem_u32(sm);
    const int t = threadIdx.x, lane = t & 31, wid = t >> 5;
    const int warpM = wid & 3, warpN = wid >> 2;
    const int bm = blockIdx.x, bn = blockIdx.y;

    float acc[2][WNS][4];
#pragma unroll
    for (int i = 0; i < 2; i++)
#pragma unroll
        for (int j = 0; j < WNS; j++)
#pragma unroll
            for (int q = 0; q < 4; q++) acc[i][j][q] = 0.f;

    auto load_chunk = [&](int c, int b) {
        const uint32_t base = S + b * STRIDE;
        for (int i = t; i < 512; i += 256) {
            int row = i >> 2, seg = i & 3;
            int gr = bm * 128 + row;
            bool v = gr < BB;
            int grc = v ? gr : (BB - 1);
            size_t off = (size_t)grc * KP + c * 32 + seg * 8;
            cp16(base + row * 80 + seg * 16, Ah + off, v);
            cp16(base + OFF_AL + row * 80 + seg * 16, Al + off, v);
        }
        for (int i = t; i < BN * 4; i += 256) {
            int row = i >> 2, seg = i & 3;
            size_t off = (size_t)(bn * BN + row) * KP + c * 32 + seg * 8;
            cp16(base + OFF_BH + row * 80 + seg * 16, Bh + off, true);
            cp16(base + OFF_BL + row * 80 + seg * 16, Bl + off, true);
        }
    };

    auto compute_chunk = [&](int bufIdx) {
        const uint32_t base = S + bufIdx * STRIDE;
        const uint32_t lrow = lane & 15;
        const uint32_t lcol = (lane >> 4) * 16;
#pragma unroll
        for (int kk = 0; kk < 2; kk++) {
            const uint32_t kb = kk * 32 + lcol;
            uint32_t a_hi[2][4], a_lo[2][4];
#pragma unroll
            for (int ms = 0; ms < 2; ms++) {
                uint32_t r0 = (warpM * 32 + ms * 16 + lrow) * 80 + kb;
                LDM_X4(a_hi[ms], base + r0);
                LDM_X4(a_lo[ms], base + OFF_AL + r0);
            }
#pragma unroll
            for (int ng = 0; ng < NG; ng++) {
                uint32_t bh[4], bl[4];
                uint32_t r0 = (warpN * WN + ng * 16 + lrow) * 80 + kb;
                LDM_X4(bh, base + OFF_BH + r0);
                LDM_X4(bl, base + OFF_BL + r0);
#pragma unroll
                for (int ms = 0; ms < 2; ms++) {
                    mma_bf16(acc[ms][2*ng],   a_hi[ms], bh[0], bh[2]);
                    mma_bf16(acc[ms][2*ng+1], a_hi[ms], bh[1], bh[3]);
                }
#pragma unroll
                for (int ms = 0; ms < 2; ms++) {
                    mma_bf16(acc[ms][2*ng],   a_hi[ms], bl[0], bl[2]);
                    mma_bf16(acc[ms][2*ng+1], a_hi[ms], bl[1], bl[3]);
                }
#pragma unroll
                for (int ms = 0; ms < 2; ms++) {
                    mma_bf16(acc[ms][2*ng],   a_lo[ms], bh[0], bh[2]);
                    mma_bf16(acc[ms][2*ng+1], a_lo[ms], bh[1], bh[3]);
                }
            }
        }
    };

    if (STAGES == 2) {
        load_chunk(0, 0); CP_COMMIT();
        for (int c = 0; c < NCH; c++) {
            if (c + 1 < NCH) { load_chunk(c + 1, (c + 1) & 1); CP_COMMIT(); CP_WAIT(1); }
            else             { CP_WAIT(0); }
            __syncthreads();
            compute_chunk(c & 1);
            __syncthreads();
        }
    } else {
        load_chunk(0, 0); CP_COMMIT();
        load_chunk(1, 1); CP_COMMIT();
        int bufc = 0;
        for (int c = 0; c < NCH; c++) {
            CP_WAIT(1);          // group c complete (pending were {c, c+1})
            __syncthreads();     // publishes chunk c; retires buf (c+2)%3 readers
            if (c + 2 < NCH) {
                int b2 = bufc + 2; if (b2 >= 3) b2 -= 3;
                load_chunk(c + 2, b2);
            }
            CP_COMMIT();         // always: uniform group counting
            compute_chunk(bufc);
            bufc = (bufc == 2) ? 0 : bufc + 1;
        }
    }

    const int g = lane >> 2, tq = lane & 3;
#pragma unroll
    for (int ms = 0; ms < 2; ms++) {
#pragma unroll
        for (int ns = 0; ns < WNS; ns++) {
            int row = bm * 128 + warpM * 32 + ms * 16 + g;
            int col = bn * BN + warpN * WN + ns * 8 + tq * 2;
#pragma unroll
            for (int half = 0; half < 2; half++) {
                int r = row + half * 8;
                if (r >= BB) continue;
                float v0 = acc[ms][ns][half * 2 + 0];
                float v1 = acc[ms][ns][half * 2 + 1];
                if (FUSE) {
                    if (col >= QD) continue;
                    float2 res;
                    if (col < NODE_D) res = *(const float2*)(nodef + (size_t)r * NODE_D + col);
                    else              res = *(const float2*)(ntime + (size_t)r * TIME_D + (col - NODE_D));
                    float2 bb = *(const float2*)(br + col);
                    v0 += bb.x + res.x;
                    v1 += bb.y + res.y;
                }
                *(float2*)(outp + (size_t)r * OSTR + col) = make_float2(v0, v1);
            }
        }
    }
}

// ---------------- K2: streaming attention, one CTA per root row (R6 config) ---
__global__ __launch_bounds__(320)
void k_attn(const float* __restrict__ nbr_node, const float* __restrict__ nbr_time,
            const float* __restrict__ nbr_edge, const int* __restrict__ masks,
            float* __restrict__ out)
{
    __shared__ __align__(16) float kv[NN * KD];   // 35520 B
    __shared__ __align__(16) float qts[QT];       // 3552 B
    __shared__ float sc[NH * NN];

    const int b = blockIdx.x;
    const int t = threadIdx.x;
    const int w = t >> 5, lane = t & 31;
    const uint32_t kvS  = smem_u32(kv);
    const uint32_t qtsS = smem_u32(qts);

    for (int i = t; i < NN * (NODE_D / 4); i += 320) {
        int n = i / (NODE_D / 4), j4 = i % (NODE_D / 4);
        cp16(kvS + (n * KD + j4 * 4) * 4,
             nbr_node + ((size_t)b * NN + n) * NODE_D + j4 * 4, true);
    }
    for (int i = t; i < NN * (EDGE_D / 4); i += 320) {
        int n = i / (EDGE_D / 4), j4 = i % (EDGE_D / 4);
        cp16(kvS + (n * KD + NODE_D + j4 * 4) * 4,
             nbr_edge + ((size_t)b * NN + n) * EDGE_D + j4 * 4, true);
    }
    for (int i = t; i < NN * (TIME_D / 4); i += 320) {
        int n = i / (TIME_D / 4), j4 = i % (TIME_D / 4);
        cp16(kvS + (n * KD + NODE_D + EDGE_D + j4 * 4) * 4,
             nbr_time + ((size_t)b * NN + n) * TIME_D + j4 * 4, true);
    }
    for (int i = t; i < QT / 4; i += 320)
        cp16(qtsS + i * 16, g_qt + (size_t)b * NPAD1 + i * 4, true);
    CP_COMMIT();
    CP_WAIT(0);
    __syncthreads();

    {
        const int n0 = 2 * w, n1 = 2 * w + 1;
        float a00 = 0.f, a01 = 0.f, a10 = 0.f, a11 = 0.f;
        for (int j = lane; j < KD; j += 32) {
            float q0 = qts[j], q1 = qts[KD + j];
            float k0 = kv[n0 * KD + j], k1 = kv[n1 * KD + j];
            a00 += q0 * k0; a01 += q0 * k1;
            a10 += q1 * k0; a11 += q1 * k1;
        }
#pragma unroll
        for (int o = 16; o; o >>= 1) {
            a00 += __shfl_xor_sync(0xffffffffu, a00, o);
            a01 += __shfl_xor_sync(0xffffffffu, a01, o);
            a10 += __shfl_xor_sync(0xffffffffu, a10, o);
            a11 += __shfl_xor_sync(0xffffffffu, a11, o);
        }
        if (lane == 0) {
            int m0 = masks[(size_t)b * NN + n0];
            int m1 = masks[(size_t)b * NN + n1];
            sc[n0]      = (m0 == 0) ? -1e10f : a00 * ATTN_SCALE;
            sc[n1]      = (m1 == 0) ? -1e10f : a01 * ATTN_SCALE;
            sc[NN + n0] = (m0 == 0) ? -1e10f : a10 * ATTN_SCALE;
            sc[NN + n1] = (m1 == 0) ? -1e10f : a11 * ATTN_SCALE;
        }
    }
    __syncthreads();

    if (w < NH) {
        const int h = w;
        float x = (lane < NN) ? sc[h * NN + lane] : -INFINITY;
        float m = x;
#pragma unroll
        for (int o = 16; o; o >>= 1) m = fmaxf(m, __shfl_xor_sync(0xffffffffu, m, o));
        float e = (lane < NN) ? __expf(x - m) : 0.f;
        float ssum = e;
#pragma unroll
        for (int o = 16; o; o >>= 1) ssum += __shfl_xor_sync(0xffffffffu, ssum, o);
        float a = e / ssum;
        if (lane < NN) {
            sc[h * NN + lane] = a;
            out[(size_t)BB * QD + ((size_t)b * NH + h) * NN + lane] = a;
        }
    }
    __syncthreads();

    for (int j = t; j < KD; j += 320) {
        float c0 = 0.f, c1 = 0.f;
#pragma unroll
        for (int n = 0; n < NN; ++n) {
            float kvv = kv[n * KD + j];
            c0 += sc[n] * kvv;
            c1 += sc[NN + n] * kvv;
        }
        __nv_bfloat16 h0 = __float2bfloat16(c0);
        __nv_bfloat16 h1 = __float2bfloat16(c1);
        size_t base = (size_t)b * KPAD2;
        g_cxh[base + j]      = h0;
        g_cxl[base + j]      = __float2bfloat16(c0 - __bfloat162float(h0));
        g_cxh[base + KD + j] = h1;
        g_cxl[base + KD + j] = __float2bfloat16(c1 - __bfloat162float(h1));
    }
    if (t < KPAD2 - QT) {
        g_cxh[(size_t)b * KPAD2 + QT + t] = __float2bfloat16(0.f);
        g_cxl[(size_t)b * KPAD2 + QT + t] = __float2bfloat16(0.f);
    }
}

// ---------------- LayerNorm, one warp per row ---------------------------------
__global__ __launch_bounds__(256)
void k_ln(const float* __restrict__ gamma, const float* __restrict__ beta,
          float* __restrict__ out)
{
    int gw   = (blockIdx.x * blockDim.x + threadIdx.x) >> 5;
    int lane = threadIdx.x & 31;
    if (gw >= BB) return;
    const float* x = g_x + (size_t)gw * QD;
    float s = 0.f, s2 = 0.f;
    for (int j = lane; j < QD; j += 32) { float v = x[j]; s += v; s2 += v * v; }
#pragma unroll
    for (int o = 16; o; o >>= 1) {
        s  += __shfl_xor_sync(0xffffffffu, s,  o);
        s2 += __shfl_xor_sync(0xffffffffu, s2, o);
    }
    float mu   = s * (1.f / QD);
    float var  = s2 * (1.f / QD) - mu * mu;
    float rstd = rsqrtf(var + LN_EPS);
    for (int j = lane; j < QD; j += 32)
        out[(size_t)gw * QD + j] = (x[j] - mu) * rstd * gamma[j] + beta[j];
}

// ---------------- side stream for fold_Rv (created once, outside capture) -----
struct SideRes {
    cudaStream_t s1;
    cudaEvent_t root, done;
    SideRes() {
        cudaStreamCreateWithFlags(&s1, cudaStreamNonBlocking);
        cudaEventCreateWithFlags(&root, cudaEventDisableTiming);
        cudaEventCreateWithFlags(&done, cudaEventDisableTiming);
    }
};
static SideRes g_side;

// ---------------- launch ------------------------------------------------------
#define SMEM1 (2 * (4 * 128 * 2 * RSTR))                       // 81920 (2-stage, BN=128)
#define SMEM2 (3 * (2 * 128 * 2 * RSTR + 2 * 96 * 2 * RSTR))   // 107520 (3-stage, BN=96)

extern "C" void kernel_launch(void* const* d_in, const int* in_sizes, int n_in,
                              void* d_out, int out_size)
{
    const float* nodef    = (const float*)d_in[0];
    const float* ntime    = (const float*)d_in[1];
    const float* nbr_node = (const float*)d_in[2];
    const float* nbr_time = (const float*)d_in[3];
    const float* nbr_edge = (const float*)d_in[4];
    const int*   masks    = (const int*)  d_in[5];
    const float* Wq       = (const float*)d_in[6];
    const float* Wk       = (const float*)d_in[7];
    const float* Wv       = (const float*)d_in[8];
    const float* Wr       = (const float*)d_in[9];
    const float* br       = (const float*)d_in[10];
    const float* gamma    = (const float*)d_in[11];
    const float* beta     = (const float*)d_in[12];
    float* out = (float*)d_out;

    auto g1 = k_gemm_mma<128, NCHUNK1, KPAD1, NPAD1, false, 1, 2>;
    auto g2 = k_gemm_mma<96,  NCHUNK2, KPAD2, QD,    true,  2, 3>;
    cudaFuncSetAttribute(g1, cudaFuncAttributeMaxDynamicSharedMemorySize, SMEM1);
    cudaFuncSetAttribute(g2, cudaFuncAttributeMaxDynamicSharedMemorySize, SMEM2);

    // fold_Rv on a side stream — only needed before G2, overlaps G1+attn
    cudaEventRecord(g_side.root, 0);
    cudaStreamWaitEvent(g_side.s1, g_side.root, 0);
    k_fold_Rv<<<(NPAD2 * KPAD2 + 255) / 256, 256, 0, g_side.s1>>>(Wr, Wv);
    cudaEventRecord(g_side.done, g_side.s1);

    // main stream
    k_prep_qin<<<(BB * KPAD1 + 255) / 256, 256>>>(nodef, ntime);
    k_fold_M <<<(NPAD1 * KPAD1 + 255) / 256, 256>>>(Wq, Wk);

    dim3 grid1((BB + 127) / 128, NPAD1 / 128);
    g1<<<grid1, 256, SMEM1>>>(nodef, ntime, br);

    k_attn<<<BB, 320>>>(nbr_node, nbr_time, nbr_edge, masks, out);

    cudaStreamWaitEvent(0, g_side.done, 0);
    dim3 grid2((BB + 127) / 128, NPAD2 / 96);
    g2<<<grid2, 256, SMEM2>>>(nodef, ntime, br);

    k_ln<<<(BB * 32 + 255) / 256, 256>>>(gamma, beta, out);
}

// round 12
// speedup vs baseline: 1.6991x; 1.1029x over previous
#include <cuda_runtime.h>
#include <cuda_bf16.h>
#include <cstdint>

#define BB      20000
#define NN      20
#define NODE_D  172
#define EDGE_D  172
#define TIME_D  100
#define QD      272          // NODE_D + TIME_D
#define KD      444          // NODE_D + EDGE_D + TIME_D
#define NH      2
#define HD      136
#define QT      (NH*KD)      // 888
#define ATTN_SCALE 0.08574929257125442f   // 136^-0.5
#define LN_EPS  1e-5f

// GEMM geometry (K-chunk = 32 bf16)
#define KPAD1   288          // GEMM1 K (272 -> 9 chunks)
#define NPAD1   896          // GEMM1 N (888 -> 7 tiles of 128)
#define KPAD2   896          // GEMM2 K (888 -> 28 chunks)
#define NPAD2   288          // GEMM2 N (272 -> 3 tiles of 96)
#define NCHUNK1 9
#define NCHUNK2 28
#define RSTR    40           // smem row stride in bf16 (80 B)

// ---------------- scratch -----------------------------------------------------
__device__ __align__(16) __nv_bfloat16 g_qin_hi[(size_t)BB * KPAD1];
__device__ __align__(16) __nv_bfloat16 g_qin_lo[(size_t)BB * KPAD1];
__device__ __align__(16) __nv_bfloat16 g_Mhi[NPAD1 * KPAD1];
__device__ __align__(16) __nv_bfloat16 g_Mlo[NPAD1 * KPAD1];
__device__ __align__(16) __nv_bfloat16 g_Rvhi[NPAD2 * KPAD2];
__device__ __align__(16) __nv_bfloat16 g_Rvlo[NPAD2 * KPAD2];
__device__ __align__(16) float         g_qt[(size_t)BB * NPAD1];
__device__ __align__(16) __nv_bfloat16 g_cxh[(size_t)BB * KPAD2];
__device__ __align__(16) __nv_bfloat16 g_cxl[(size_t)BB * KPAD2];
__device__ __align__(16) float         g_x[(size_t)BB * QD];

// ---------------- helpers -----------------------------------------------------
__device__ __forceinline__ uint32_t smem_u32(const void* p) {
    uint32_t a;
    asm("{ .reg .u64 t; cvta.to.shared.u64 t, %1; cvt.u32.u64 %0, t; }" : "=r"(a) : "l"(p));
    return a;
}
__device__ __forceinline__ void cp16(uint32_t dst, const void* src, bool v) {
    int sz = v ? 16 : 0;
    asm volatile("cp.async.cg.shared.global [%0], [%1], 16, %2;"
                 :: "r"(dst), "l"(src), "r"(sz));
}
#define CP_COMMIT() asm volatile("cp.async.commit_group;" ::: "memory")
#define CP_WAIT(n)  asm volatile("cp.async.wait_group %0;" :: "n"(n) : "memory")

#define LDM_X4(r, a) \
    asm volatile("ldmatrix.sync.aligned.m8n8.x4.shared.b16 {%0,%1,%2,%3}, [%4];" \
                 : "=r"((r)[0]), "=r"((r)[1]), "=r"((r)[2]), "=r"((r)[3]) : "r"(a))

__device__ __forceinline__ void mma_bf16(float* c, const uint32_t a[4],
                                         uint32_t b0, uint32_t b1) {
    asm volatile(
        "mma.sync.aligned.m16n8k16.row.col.f32.bf16.bf16.f32 "
        "{%0,%1,%2,%3}, {%4,%5,%6,%7}, {%8,%9}, {%0,%1,%2,%3};"
        : "+f"(c[0]), "+f"(c[1]), "+f"(c[2]), "+f"(c[3])
        : "r"(a[0]), "r"(a[1]), "r"(a[2]), "r"(a[3]), "r"(b0), "r"(b1));
}

__device__ __forceinline__ void split_bf16(float x, __nv_bfloat16& h, __nv_bfloat16& l) {
    h = __float2bfloat16(x);
    l = __float2bfloat16(x - __bfloat162float(h));
}

// ---------------- prep: qin = concat(nodef, ntime) -> hi/lo bf16 [B, 288] -----
__global__ void k_prep_qin(const float* __restrict__ nodef, const float* __restrict__ ntime)
{
    int i = blockIdx.x * blockDim.x + threadIdx.x;
    if (i >= BB * KPAD1) return;
    int r = i / KPAD1, c = i % KPAD1;
    float x = 0.f;
    if (c < NODE_D)   x = nodef[(size_t)r * NODE_D + c];
    else if (c < QD)  x = ntime[(size_t)r * TIME_D + (c - NODE_D)];
    __nv_bfloat16 h, l; split_bf16(x, h, l);
    g_qin_hi[i] = h; g_qin_lo[i] = l;
}

// ---------------- fold M = Wk^T Wq per head -> hi/lo [896, 288] ---------------
__global__ void k_fold_M(const float* __restrict__ Wq, const float* __restrict__ Wk)
{
    int tid = blockIdx.x * blockDim.x + threadIdx.x;
    if (tid >= NPAD1 * KPAD1) return;
    int c = tid % KPAD1;
    int o = tid / KPAD1;
    float acc = 0.f;
    if (o < QT && c < QD) {
        int h = o / KD, j = o % KD;
        const float* wk = Wk + (size_t)(h * HD) * KD + j;
        const float* wq = Wq + (size_t)(h * HD) * QD + c;
#pragma unroll 8
        for (int d = 0; d < HD; ++d)
            acc += wk[(size_t)d * KD] * wq[(size_t)d * QD];
    }
    __nv_bfloat16 h16, l16; split_bf16(acc, h16, l16);
    g_Mhi[tid] = h16; g_Mlo[tid] = l16;
}

// ---------------- fold Rv = Wr Wv per head -> hi/lo [288, 896] ----------------
__global__ void k_fold_Rv(const float* __restrict__ Wr, const float* __restrict__ Wv)
{
    int tid = blockIdx.x * blockDim.x + threadIdx.x;
    if (tid >= NPAD2 * KPAD2) return;
    int p = tid % KPAD2;
    int o = tid / KPAD2;
    float acc = 0.f;
    if (o < QD && p < QT) {
        int h = p / KD, j = p % KD;
        const float* wr = Wr + (size_t)o * QD + h * HD;
        const float* wv = Wv + (size_t)(h * HD) * KD + j;
#pragma unroll 8
        for (int d = 0; d < HD; ++d)
            acc += wr[d] * wv[(size_t)d * KD];
    }
    __nv_bfloat16 h16, l16; split_bf16(acc, h16, l16);
    g_Rvhi[tid] = h16; g_Rvlo[tid] = l16;
}

// ---------------- bf16x3 HMMA GEMM (R11: STAGES=2 or 3) -----------------------
template<int BN, int NCH, int KP, int OSTR, bool FUSE, int WHICH, int STAGES>
__global__ __launch_bounds__(256)
void k_gemm_mma(const float* __restrict__ nodef, const float* __restrict__ ntime,
                const float* __restrict__ br)
{
    const __nv_bfloat16* __restrict__ Ah = (WHICH == 1) ? g_qin_hi : g_cxh;
    const __nv_bfloat16* __restrict__ Al = (WHICH == 1) ? g_qin_lo : g_cxl;
    const __nv_bfloat16* __restrict__ Bh = (WHICH == 1) ? g_Mhi : g_Rvhi;
    const __nv_bfloat16* __restrict__ Bl = (WHICH == 1) ? g_Mlo : g_Rvlo;
    float* __restrict__ outp             = (WHICH == 1) ? g_qt : g_x;

    constexpr int WN   = BN / 2;
    constexpr int WNS  = WN / 8;
    constexpr int NG   = WN / 16;
    constexpr int OFF_AL = 128 * 2 * RSTR;
    constexpr int OFF_BH = 2 * OFF_AL;
    constexpr int OFF_BL = OFF_BH + BN * 2 * RSTR;
    constexpr int STRIDE = OFF_BL + BN * 2 * RSTR;

    extern __shared__ char sm[];
    const uint32_t S = smem_u32(sm);
    const int t = threadIdx.x, lane = t & 31, wid = t >> 5;
    const int warpM = wid & 3, warpN = wid >> 2;
    const int bm = blockIdx.x, bn = blockIdx.y;

    float acc[2][WNS][4];
#pragma unroll
    for (int i = 0; i < 2; i++)
#pragma unroll
        for (int j = 0; j < WNS; j++)
#pragma unroll
            for (int q = 0; q < 4; q++) acc[i][j][q] = 0.f;

    auto load_chunk = [&](int c, int b) {
        const uint32_t base = S + b * STRIDE;
        for (int i = t; i < 512; i += 256) {
            int row = i >> 2, seg = i & 3;
            int gr = bm * 128 + row;
            bool v = gr < BB;
            int grc = v ? gr : (BB - 1);
            size_t off = (size_t)grc * KP + c * 32 + seg * 8;
            cp16(base + row * 80 + seg * 16, Ah + off, v);
            cp16(base + OFF_AL + row * 80 + seg * 16, Al + off, v);
        }
        for (int i = t; i < BN * 4; i += 256) {
            int row = i >> 2, seg = i & 3;
            size_t off = (size_t)(bn * BN + row) * KP + c * 32 + seg * 8;
            cp16(base + OFF_BH + row * 80 + seg * 16, Bh + off, true);
            cp16(base + OFF_BL + row * 80 + seg * 16, Bl + off, true);
        }
    };

    auto compute_chunk = [&](int bufIdx) {
        const uint32_t base = S + bufIdx * STRIDE;
        const uint32_t lrow = lane & 15;
        const uint32_t lcol = (lane >> 4) * 16;
#pragma unroll
        for (int kk = 0; kk < 2; kk++) {
            const uint32_t kb = kk * 32 + lcol;
            uint32_t a_hi[2][4], a_lo[2][4];
#pragma unroll
            for (int ms = 0; ms < 2; ms++) {
                uint32_t r0 = (warpM * 32 + ms * 16 + lrow) * 80 + kb;
                LDM_X4(a_hi[ms], base + r0);
                LDM_X4(a_lo[ms], base + OFF_AL + r0);
            }
#pragma unroll
            for (int ng = 0; ng < NG; ng++) {
                uint32_t bh[4], bl[4];
                uint32_t r0 = (warpN * WN + ng * 16 + lrow) * 80 + kb;
                LDM_X4(bh, base + OFF_BH + r0);
                LDM_X4(bl, base + OFF_BL + r0);
#pragma unroll
                for (int ms = 0; ms < 2; ms++) {
                    mma_bf16(acc[ms][2*ng],   a_hi[ms], bh[0], bh[2]);
                    mma_bf16(acc[ms][2*ng+1], a_hi[ms], bh[1], bh[3]);
                }
#pragma unroll
                for (int ms = 0; ms < 2; ms++) {
                    mma_bf16(acc[ms][2*ng],   a_hi[ms], bl[0], bl[2]);
                    mma_bf16(acc[ms][2*ng+1], a_hi[ms], bl[1], bl[3]);
                }
#pragma unroll
                for (int ms = 0; ms < 2; ms++) {
                    mma_bf16(acc[ms][2*ng],   a_lo[ms], bh[0], bh[2]);
                    mma_bf16(acc[ms][2*ng+1], a_lo[ms], bh[1], bh[3]);
                }
            }
        }
    };

    if (STAGES == 2) {
        load_chunk(0, 0); CP_COMMIT();
        for (int c = 0; c < NCH; c++) {
            if (c + 1 < NCH) { load_chunk(c + 1, (c + 1) & 1); CP_COMMIT(); CP_WAIT(1); }
            else             { CP_WAIT(0); }
            __syncthreads();
            compute_chunk(c & 1);
            __syncthreads();
        }
    } else {
        load_chunk(0, 0); CP_COMMIT();
        load_chunk(1, 1); CP_COMMIT();
        int bufc = 0;
        for (int c = 0; c < NCH; c++) {
            CP_WAIT(1);
            __syncthreads();
            if (c + 2 < NCH) {
                int b2 = bufc + 2; if (b2 >= 3) b2 -= 3;
                load_chunk(c + 2, b2);
            }
            CP_COMMIT();
            compute_chunk(bufc);
            bufc = (bufc == 2) ? 0 : bufc + 1;
        }
    }

    const int g = lane >> 2, tq = lane & 3;
#pragma unroll
    for (int ms = 0; ms < 2; ms++) {
#pragma unroll
        for (int ns = 0; ns < WNS; ns++) {
            int row = bm * 128 + warpM * 32 + ms * 16 + g;
            int col = bn * BN + warpN * WN + ns * 8 + tq * 2;
#pragma unroll
            for (int half = 0; half < 2; half++) {
                int r = row + half * 8;
                if (r >= BB) continue;
                float v0 = acc[ms][ns][half * 2 + 0];
                float v1 = acc[ms][ns][half * 2 + 1];
                if (FUSE) {
                    if (col >= QD) continue;
                    float2 res;
                    if (col < NODE_D) res = *(const float2*)(nodef + (size_t)r * NODE_D + col);
                    else              res = *(const float2*)(ntime + (size_t)r * TIME_D + (col - NODE_D));
                    float2 bb = *(const float2*)(br + col);
                    v0 += bb.x + res.x;
                    v1 += bb.y + res.y;
                }
                *(float2*)(outp + (size_t)r * OSTR + col) = make_float2(v0, v1);
            }
        }
    }
}

// ---------------- K2: mask-compacted streaming attention ----------------------
// Reads masks FIRST; only active neighbor rows are loaded (compact slots).
// Masked neighbors contribute exactly 0 (exp(-1e10 - m) == 0 in fp32), matching
// the reference bit-for-bit. All-masked rows (P ~ 1e-6/row) fall back to
// score=0 for all neighbors -> uniform softmax, identical to reference.
__global__ __launch_bounds__(320)
void k_attn(const float* __restrict__ nbr_node, const float* __restrict__ nbr_time,
            const float* __restrict__ nbr_edge, const int* __restrict__ masks,
            float* __restrict__ out)
{
    __shared__ __align__(16) float kv[NN * KD];   // compact slots
    __shared__ __align__(16) float qts[QT];
    __shared__ float sc[NH * NN];                 // scores/attn by neighbor idx
    __shared__ float aw[NH * NN];                 // attn by compact slot

    const int b = blockIdx.x;
    const int t = threadIdx.x;
    const int w = t >> 5, lane = t & 31;
    const uint32_t kvS  = smem_u32(kv);
    const uint32_t qtsS = smem_u32(qts);

    // ---- masks -> active bitmask (same value in every warp) ----
    int mv = (lane < NN) ? (masks[(size_t)b * NN + lane] != 0) : 0;
    uint32_t mb = __ballot_sync(0xffffffffu, mv) & 0xFFFFFu;
    const bool allmask = (mb == 0);
    if (allmask) mb = 0xFFFFFu;
    const int nact = __popc(mb);

    // ---- stage qts + ACTIVE kv rows (compacted) via cp.async ----
    for (int i = t; i < QT / 4; i += 320)
        cp16(qtsS + i * 16, g_qt + (size_t)b * NPAD1 + i * 4, true);
    for (int i = t; i < nact * (NODE_D / 4); i += 320) {
        int s = i / (NODE_D / 4), j4 = i % (NODE_D / 4);
        int n = __fns(mb, 0, s + 1);
        cp16(kvS + (s * KD + j4 * 4) * 4,
             nbr_node + ((size_t)b * NN + n) * NODE_D + j4 * 4, true);
    }
    for (int i = t; i < nact * (EDGE_D / 4); i += 320) {
        int s = i / (EDGE_D / 4), j4 = i % (EDGE_D / 4);
        int n = __fns(mb, 0, s + 1);
        cp16(kvS + (s * KD + NODE_D + j4 * 4) * 4,
             nbr_edge + ((size_t)b * NN + n) * EDGE_D + j4 * 4, true);
    }
    for (int i = t; i < nact * (TIME_D / 4); i += 320) {
        int s = i / (TIME_D / 4), j4 = i % (TIME_D / 4);
        int n = __fns(mb, 0, s + 1);
        cp16(kvS + (s * KD + NODE_D + EDGE_D + j4 * 4) * 4,
             nbr_time + ((size_t)b * NN + n) * TIME_D + j4 * 4, true);
    }
    if (t < NH * NN) sc[t] = -1e10f;   // default: masked
    CP_COMMIT();
    CP_WAIT(0);
    __syncthreads();

    // ---- scores: warp w -> compact slots 2w, 2w+1 (both heads) ----
    {
        const int s0 = 2 * w, s1 = 2 * w + 1;
        if (s0 < nact) {
            const bool has1 = (s1 < nact);
            const int n0 = __fns(mb, 0, s0 + 1);
            const int n1 = has1 ? __fns(mb, 0, s1 + 1) : 0;
            float a00 = 0.f, a01 = 0.f, a10 = 0.f, a11 = 0.f;
            for (int j = lane; j < KD; j += 32) {
                float q0 = qts[j], q1 = qts[KD + j];
                float k0 = kv[s0 * KD + j];
                float k1 = kv[s1 * KD + j];   // s1<20 always; garbage unused if !has1
                a00 += q0 * k0; a01 += q0 * k1;
                a10 += q1 * k0; a11 += q1 * k1;
            }
#pragma unroll
            for (int o = 16; o; o >>= 1) {
                a00 += __shfl_xor_sync(0xffffffffu, a00, o);
                a01 += __shfl_xor_sync(0xffffffffu, a01, o);
                a10 += __shfl_xor_sync(0xffffffffu, a10, o);
                a11 += __shfl_xor_sync(0xffffffffu, a11, o);
            }
            if (lane == 0) {
                sc[n0]      = allmask ? 0.f : a00 * ATTN_SCALE;
                sc[NN + n0] = allmask ? 0.f : a10 * ATTN_SCALE;
                if (has1) {
                    sc[n1]      = allmask ? 0.f : a01 * ATTN_SCALE;
                    sc[NN + n1] = allmask ? 0.f : a11 * ATTN_SCALE;
                }
            }
        }
    }
    __syncthreads();

    // ---- softmax: warp h handles head h; write attn output + slot weights ----
    if (w < NH) {
        const int h = w;
        float x = (lane < NN) ? sc[h * NN + lane] : -INFINITY;
        float m = x;
#pragma unroll
        for (int o = 16; o; o >>= 1) m = fmaxf(m, __shfl_xor_sync(0xffffffffu, m, o));
        float e = (lane < NN) ? __expf(x - m) : 0.f;
        float ssum = e;
#pragma unroll
        for (int o = 16; o; o >>= 1) ssum += __shfl_xor_sync(0xffffffffu, ssum, o);
        float a = e / ssum;
        if (lane < NN) {
            out[(size_t)BB * QD + ((size_t)b * NH + h) * NN + lane] = a;
            if ((mb >> lane) & 1u) {
                int s = __popc(mb & ((1u << lane) - 1u));
                aw[h * NN + s] = a;
            }
        }
    }
    __syncthreads();

    // ---- ctx: sum over ACTIVE slots, both heads per element ----
    for (int j = t; j < KD; j += 320) {
        float c0 = 0.f, c1 = 0.f;
        for (int s = 0; s < nact; ++s) {
            float kvv = kv[s * KD + j];
            c0 += aw[s] * kvv;
            c1 += aw[NN + s] * kvv;
        }
        __nv_bfloat16 h0 = __float2bfloat16(c0);
        __nv_bfloat16 h1 = __float2bfloat16(c1);
        size_t base = (size_t)b * KPAD2;
        g_cxh[base + j]      = h0;
        g_cxl[base + j]      = __float2bfloat16(c0 - __bfloat162float(h0));
        g_cxh[base + KD + j] = h1;
        g_cxl[base + KD + j] = __float2bfloat16(c1 - __bfloat162float(h1));
    }
    if (t < KPAD2 - QT) {
        g_cxh[(size_t)b * KPAD2 + QT + t] = __float2bfloat16(0.f);
        g_cxl[(size_t)b * KPAD2 + QT + t] = __float2bfloat16(0.f);
    }
}

// ---------------- LayerNorm, one warp per row ---------------------------------
__global__ __launch_bounds__(256)
void k_ln(const float* __restrict__ gamma, const float* __restrict__ beta,
          float* __restrict__ out)
{
    int gw   = (blockIdx.x * blockDim.x + threadIdx.x) >> 5;
    int lane = threadIdx.x & 31;
    if (gw >= BB) return;
    const float* x = g_x + (size_t)gw * QD;
    float s = 0.f, s2 = 0.f;
    for (int j = lane; j < QD; j += 32) { float v = x[j]; s += v; s2 += v * v; }
#pragma unroll
    for (int o = 16; o; o >>= 1) {
        s  += __shfl_xor_sync(0xffffffffu, s,  o);
        s2 += __shfl_xor_sync(0xffffffffu, s2, o);
    }
    float mu   = s * (1.f / QD);
    float var  = s2 * (1.f / QD) - mu * mu;
    float rstd = rsqrtf(var + LN_EPS);
    for (int j = lane; j < QD; j += 32)
        out[(size_t)gw * QD + j] = (x[j] - mu) * rstd * gamma[j] + beta[j];
}

// ---------------- side stream for weight folds (created once, outside capture)
struct SideRes {
    cudaStream_t s1;
    cudaEvent_t root, eFM, eFRV;
    SideRes() {
        cudaStreamCreateWithFlags(&s1, cudaStreamNonBlocking);
        cudaEventCreateWithFlags(&root, cudaEventDisableTiming);
        cudaEventCreateWithFlags(&eFM,  cudaEventDisableTiming);
        cudaEventCreateWithFlags(&eFRV, cudaEventDisableTiming);
    }
};
static SideRes g_side;

// ---------------- launch ------------------------------------------------------
#define SMEM1 (2 * (4 * 128 * 2 * RSTR))                       // 81920 (2-stage, BN=128)
#define SMEM2 (3 * (2 * 128 * 2 * RSTR + 2 * 96 * 2 * RSTR))   // 107520 (3-stage, BN=96)

extern "C" void kernel_launch(void* const* d_in, const int* in_sizes, int n_in,
                              void* d_out, int out_size)
{
    const float* nodef    = (const float*)d_in[0];
    const float* ntime    = (const float*)d_in[1];
    const float* nbr_node = (const float*)d_in[2];
    const float* nbr_time = (const float*)d_in[3];
    const float* nbr_edge = (const float*)d_in[4];
    const int*   masks    = (const int*)  d_in[5];
    const float* Wq       = (const float*)d_in[6];
    const float* Wk       = (const float*)d_in[7];
    const float* Wv       = (const float*)d_in[8];
    const float* Wr       = (const float*)d_in[9];
    const float* br       = (const float*)d_in[10];
    const float* gamma    = (const float*)d_in[11];
    const float* beta     = (const float*)d_in[12];
    float* out = (float*)d_out;

    auto g1 = k_gemm_mma<128, NCHUNK1, KPAD1, NPAD1, false, 1, 2>;
    auto g2 = k_gemm_mma<96,  NCHUNK2, KPAD2, QD,    true,  2, 3>;
    cudaFuncSetAttribute(g1, cudaFuncAttributeMaxDynamicSharedMemorySize, SMEM1);
    cudaFuncSetAttribute(g2, cudaFuncAttributeMaxDynamicSharedMemorySize, SMEM2);

    // weight folds on a side stream — overlap with prep_qin
    cudaEventRecord(g_side.root, 0);
    cudaStreamWaitEvent(g_side.s1, g_side.root, 0);
    k_fold_M <<<(NPAD1 * KPAD1 + 255) / 256, 256, 0, g_side.s1>>>(Wq, Wk);
    cudaEventRecord(g_side.eFM, g_side.s1);
    k_fold_Rv<<<(NPAD2 * KPAD2 + 255) / 256, 256, 0, g_side.s1>>>(Wr, Wv);
    cudaEventRecord(g_side.eFRV, g_side.s1);

    // main stream
    k_prep_qin<<<(BB * KPAD1 + 255) / 256, 256>>>(nodef, ntime);

    cudaStreamWaitEvent(0, g_side.eFM, 0);
    dim3 grid1((BB + 127) / 128, NPAD1 / 128);
    g1<<<grid1, 256, SMEM1>>>(nodef, ntime, br);

    k_attn<<<BB, 320>>>(nbr_node, nbr_time, nbr_edge, masks, out);

    cudaStreamWaitEvent(0, g_side.eFRV, 0);
    dim3 grid2((BB + 127) / 128, NPAD2 / 96);
    g2<<<grid2, 256, SMEM2>>>(nodef, ntime, br);

    k_ln<<<(BB * 32 + 255) / 256, 256>>>(gamma, beta, out);
}

// round 13
// speedup vs baseline: 1.7302x; 1.0183x over previous
#include <cuda_runtime.h>
#include <cuda_bf16.h>
#include <cstdint>

#define BB      20000
#define NN      20
#define NODE_D  172
#define EDGE_D  172
#define TIME_D  100
#define QD      272          // NODE_D + TIME_D
#define KD      444          // NODE_D + EDGE_D + TIME_D
#define NH      2
#define HD      136
#define QT      (NH*KD)      // 888
#define ATTN_SCALE 0.08574929257125442f   // 136^-0.5
#define LN_EPS  1e-5f

// GEMM geometry (K-chunk = 32 bf16)
#define KPAD1   288          // GEMM1 K (272 -> 9 chunks; last chunk half-real)
#define NPAD1   896          // GEMM1 N (888 -> 7 tiles of 128)
#define KPAD2   896          // GEMM2 K (888 -> 28 chunks)
#define NPAD2   288          // GEMM2 N (272 -> 3 tiles of 96)
#define NCHUNK1 9
#define NCHUNK2 28
#define RSTR    40           // smem row stride in bf16 (80 B)

// ---------------- scratch -----------------------------------------------------
__device__ __align__(16) __nv_bfloat16 g_qin_hi[(size_t)BB * KPAD1];
__device__ __align__(16) __nv_bfloat16 g_qin_lo[(size_t)BB * KPAD1];
__device__ __align__(16) __nv_bfloat16 g_Mhi[NPAD1 * KPAD1];
__device__ __align__(16) __nv_bfloat16 g_Mlo[NPAD1 * KPAD1];
__device__ __align__(16) __nv_bfloat16 g_Rvhi[NPAD2 * KPAD2];
__device__ __align__(16) __nv_bfloat16 g_Rvlo[NPAD2 * KPAD2];
__device__ __align__(16) float         g_qt[(size_t)BB * NPAD1];
__device__ __align__(16) __nv_bfloat16 g_cxh[(size_t)BB * KPAD2];
__device__ __align__(16) __nv_bfloat16 g_cxl[(size_t)BB * KPAD2];
__device__ __align__(16) float         g_x[(size_t)BB * QD];

// ---------------- helpers -----------------------------------------------------
__device__ __forceinline__ uint32_t smem_u32(const void* p) {
    uint32_t a;
    asm("{ .reg .u64 t; cvta.to.shared.u64 t, %1; cvt.u32.u64 %0, t; }" : "=r"(a) : "l"(p));
    return a;
}
__device__ __forceinline__ void cp16(uint32_t dst, const void* src, bool v) {
    int sz = v ? 16 : 0;
    asm volatile("cp.async.cg.shared.global [%0], [%1], 16, %2;"
                 :: "r"(dst), "l"(src), "r"(sz));
}
#define CP_COMMIT() asm volatile("cp.async.commit_group;" ::: "memory")
#define CP_WAIT(n)  asm volatile("cp.async.wait_group %0;" :: "n"(n) : "memory")

#define LDM_X4(r, a) \
    asm volatile("ldmatrix.sync.aligned.m8n8.x4.shared.b16 {%0,%1,%2,%3}, [%4];" \
                 : "=r"((r)[0]), "=r"((r)[1]), "=r"((r)[2]), "=r"((r)[3]) : "r"(a))

__device__ __forceinline__ void mma_bf16(float* c, const uint32_t a[4],
                                         uint32_t b0, uint32_t b1) {
    asm volatile(
        "mma.sync.aligned.m16n8k16.row.col.f32.bf16.bf16.f32 "
        "{%0,%1,%2,%3}, {%4,%5,%6,%7}, {%8,%9}, {%0,%1,%2,%3};"
        : "+f"(c[0]), "+f"(c[1]), "+f"(c[2]), "+f"(c[3])
        : "r"(a[0]), "r"(a[1]), "r"(a[2]), "r"(a[3]), "r"(b0), "r"(b1));
}

__device__ __forceinline__ void split_bf16(float x, __nv_bfloat16& h, __nv_bfloat16& l) {
    h = __float2bfloat16(x);
    l = __float2bfloat16(x - __bfloat162float(h));
}

// ---------------- prep: qin = concat(nodef, ntime) -> hi/lo bf16 [B, 288] -----
// Vectorized: one float4 in, two packed 8-byte stores out.
__global__ void k_prep_qin(const float* __restrict__ nodef, const float* __restrict__ ntime)
{
    int i = blockIdx.x * blockDim.x + threadIdx.x;   // float4-group index
    if (i >= BB * (KPAD1 / 4)) return;
    int r = i / (KPAD1 / 4), c = (i % (KPAD1 / 4)) * 4;
    float4 x = make_float4(0.f, 0.f, 0.f, 0.f);
    if (c < NODE_D)      x = *(const float4*)(nodef + (size_t)r * NODE_D + c);
    else if (c < QD)     x = *(const float4*)(ntime + (size_t)r * TIME_D + (c - NODE_D));
    uint64_t ph, pl;
    __nv_bfloat16* hh = (__nv_bfloat16*)&ph;
    __nv_bfloat16* ll = (__nv_bfloat16*)&pl;
    split_bf16(x.x, hh[0], ll[0]);
    split_bf16(x.y, hh[1], ll[1]);
    split_bf16(x.z, hh[2], ll[2]);
    split_bf16(x.w, hh[3], ll[3]);
    *(uint64_t*)(g_qin_hi + (size_t)i * 4) = ph;
    *(uint64_t*)(g_qin_lo + (size_t)i * 4) = pl;
}

// ---------------- fold M = Wk^T Wq per head -> hi/lo [896, 288] ---------------
__global__ void k_fold_M(const float* __restrict__ Wq, const float* __restrict__ Wk)
{
    int tid = blockIdx.x * blockDim.x + threadIdx.x;
    if (tid >= NPAD1 * KPAD1) return;
    int c = tid % KPAD1;
    int o = tid / KPAD1;
    float acc = 0.f;
    if (o < QT && c < QD) {
        int h = o / KD, j = o % KD;
        const float* wk = Wk + (size_t)(h * HD) * KD + j;
        const float* wq = Wq + (size_t)(h * HD) * QD + c;
#pragma unroll 8
        for (int d = 0; d < HD; ++d)
            acc += wk[(size_t)d * KD] * wq[(size_t)d * QD];
    }
    __nv_bfloat16 h16, l16; split_bf16(acc, h16, l16);
    g_Mhi[tid] = h16; g_Mlo[tid] = l16;
}

// ---------------- fold Rv = Wr Wv per head -> hi/lo [288, 896] ----------------
__global__ void k_fold_Rv(const float* __restrict__ Wr, const float* __restrict__ Wv)
{
    int tid = blockIdx.x * blockDim.x + threadIdx.x;
    if (tid >= NPAD2 * KPAD2) return;
    int p = tid % KPAD2;
    int o = tid / KPAD2;
    float acc = 0.f;
    if (o < QD && p < QT) {
        int h = p / KD, j = p % KD;
        const float* wr = Wr + (size_t)o * QD + h * HD;
        const float* wv = Wv + (size_t)(h * HD) * KD + j;
#pragma unroll 8
        for (int d = 0; d < HD; ++d)
            acc += wr[d] * wv[(size_t)d * KD];
    }
    __nv_bfloat16 h16, l16; split_bf16(acc, h16, l16);
    g_Rvhi[tid] = h16; g_Rvlo[tid] = l16;
}

// ---------------- bf16x3 HMMA GEMM --------------------------------------------
// KKLAST: number of 16-wide k-halves computed in the LAST chunk (1 for GEMM1 —
// its upper half is zero padding, MMAs there are exact no-ops and skipped).
template<int BN, int NCH, int KP, int OSTR, bool FUSE, int WHICH, int STAGES, int KKLAST>
__global__ __launch_bounds__(256)
void k_gemm_mma(const float* __restrict__ nodef, const float* __restrict__ ntime,
                const float* __restrict__ br)
{
    const __nv_bfloat16* __restrict__ Ah = (WHICH == 1) ? g_qin_hi : g_cxh;
    const __nv_bfloat16* __restrict__ Al = (WHICH == 1) ? g_qin_lo : g_cxl;
    const __nv_bfloat16* __restrict__ Bh = (WHICH == 1) ? g_Mhi : g_Rvhi;
    const __nv_bfloat16* __restrict__ Bl = (WHICH == 1) ? g_Mlo : g_Rvlo;
    float* __restrict__ outp             = (WHICH == 1) ? g_qt : g_x;

    constexpr int WN   = BN / 2;
    constexpr int WNS  = WN / 8;
    constexpr int NG   = WN / 16;
    constexpr int OFF_AL = 128 * 2 * RSTR;
    constexpr int OFF_BH = 2 * OFF_AL;
    constexpr int OFF_BL = OFF_BH + BN * 2 * RSTR;
    constexpr int STRIDE = OFF_BL + BN * 2 * RSTR;

    extern __shared__ char sm[];
    const uint32_t S = smem_u32(sm);
    const int t = threadIdx.x, lane = t & 31, wid = t >> 5;
    const int warpM = wid & 3, warpN = wid >> 2;
    const int bm = blockIdx.x, bn = blockIdx.y;

    float acc[2][WNS][4];
#pragma unroll
    for (int i = 0; i < 2; i++)
#pragma unroll
        for (int j = 0; j < WNS; j++)
#pragma unroll
            for (int q = 0; q < 4; q++) acc[i][j][q] = 0.f;

    auto load_chunk = [&](int c, int b) {
        const uint32_t base = S + b * STRIDE;
        for (int i = t; i < 512; i += 256) {
            int row = i >> 2, seg = i & 3;
            int gr = bm * 128 + row;
            bool v = gr < BB;
            int grc = v ? gr : (BB - 1);
            size_t off = (size_t)grc * KP + c * 32 + seg * 8;
            cp16(base + row * 80 + seg * 16, Ah + off, v);
            cp16(base + OFF_AL + row * 80 + seg * 16, Al + off, v);
        }
        for (int i = t; i < BN * 4; i += 256) {
            int row = i >> 2, seg = i & 3;
            size_t off = (size_t)(bn * BN + row) * KP + c * 32 + seg * 8;
            cp16(base + OFF_BH + row * 80 + seg * 16, Bh + off, true);
            cp16(base + OFF_BL + row * 80 + seg * 16, Bl + off, true);
        }
    };

    auto compute_chunk = [&](int bufIdx, int kkmax) {
        const uint32_t base = S + bufIdx * STRIDE;
        const uint32_t lrow = lane & 15;
        const uint32_t lcol = (lane >> 4) * 16;
#pragma unroll
        for (int kk = 0; kk < 2; kk++) {
            if (kk >= kkmax) break;
            const uint32_t kb = kk * 32 + lcol;
            uint32_t a_hi[2][4], a_lo[2][4];
#pragma unroll
            for (int ms = 0; ms < 2; ms++) {
                uint32_t r0 = (warpM * 32 + ms * 16 + lrow) * 80 + kb;
                LDM_X4(a_hi[ms], base + r0);
                LDM_X4(a_lo[ms], base + OFF_AL + r0);
            }
#pragma unroll
            for (int ng = 0; ng < NG; ng++) {
                uint32_t bh[4], bl[4];
                uint32_t r0 = (warpN * WN + ng * 16 + lrow) * 80 + kb;
                LDM_X4(bh, base + OFF_BH + r0);
                LDM_X4(bl, base + OFF_BL + r0);
#pragma unroll
                for (int ms = 0; ms < 2; ms++) {
                    mma_bf16(acc[ms][2*ng],   a_hi[ms], bh[0], bh[2]);
                    mma_bf16(acc[ms][2*ng+1], a_hi[ms], bh[1], bh[3]);
                }
#pragma unroll
                for (int ms = 0; ms < 2; ms++) {
                    mma_bf16(acc[ms][2*ng],   a_hi[ms], bl[0], bl[2]);
                    mma_bf16(acc[ms][2*ng+1], a_hi[ms], bl[1], bl[3]);
                }
#pragma unroll
                for (int ms = 0; ms < 2; ms++) {
                    mma_bf16(acc[ms][2*ng],   a_lo[ms], bh[0], bh[2]);
                    mma_bf16(acc[ms][2*ng+1], a_lo[ms], bh[1], bh[3]);
                }
            }
        }
    };

    if (STAGES == 2) {
        load_chunk(0, 0); CP_COMMIT();
        for (int c = 0; c < NCH; c++) {
            if (c + 1 < NCH) { load_chunk(c + 1, (c + 1) & 1); CP_COMMIT(); CP_WAIT(1); }
            else             { CP_WAIT(0); }
            __syncthreads();
            compute_chunk(c & 1, (c == NCH - 1) ? KKLAST : 2);
            __syncthreads();
        }
    } else {
        load_chunk(0, 0); CP_COMMIT();
        load_chunk(1, 1); CP_COMMIT();
        int bufc = 0;
        for (int c = 0; c < NCH; c++) {
            CP_WAIT(1);
            __syncthreads();
            if (c + 2 < NCH) {
                int b2 = bufc + 2; if (b2 >= 3) b2 -= 3;
                load_chunk(c + 2, b2);
            }
            CP_COMMIT();
            compute_chunk(bufc, (c == NCH - 1) ? KKLAST : 2);
            bufc = (bufc == 2) ? 0 : bufc + 1;
        }
    }

    const int g = lane >> 2, tq = lane & 3;
#pragma unroll
    for (int ms = 0; ms < 2; ms++) {
#pragma unroll
        for (int ns = 0; ns < WNS; ns++) {
            int row = bm * 128 + warpM * 32 + ms * 16 + g;
            int col = bn * BN + warpN * WN + ns * 8 + tq * 2;
#pragma unroll
            for (int half = 0; half < 2; half++) {
                int r = row + half * 8;
                if (r >= BB) continue;
                float v0 = acc[ms][ns][half * 2 + 0];
                float v1 = acc[ms][ns][half * 2 + 1];
                if (FUSE) {
                    if (col >= QD) continue;
                    float2 res;
                    if (col < NODE_D) res = *(const float2*)(nodef + (size_t)r * NODE_D + col);
                    else              res = *(const float2*)(ntime + (size_t)r * TIME_D + (col - NODE_D));
                    float2 bb = *(const float2*)(br + col);
                    v0 += bb.x + res.x;
                    v1 += bb.y + res.y;
                }
                *(float2*)(outp + (size_t)r * OSTR + col) = make_float2(v0, v1);
            }
        }
    }
}

// ---------------- K2: mask-compacted streaming attention ----------------------
// Score phase: warp w owns compact slots {w, w+10} -> all 10 warps busy at the
// median nact~10 (was {2w,2w+1}: half the warps idle).
__global__ __launch_bounds__(320)
void k_attn(const float* __restrict__ nbr_node, const float* __restrict__ nbr_time,
            const float* __restrict__ nbr_edge, const int* __restrict__ masks,
            float* __restrict__ out)
{
    __shared__ __align__(16) float kv[NN * KD];   // compact slots
    __shared__ __align__(16) float qts[QT];
    __shared__ float sc[NH * NN];                 // scores/attn by neighbor idx
    __shared__ float aw[NH * NN];                 // attn by compact slot

    const int b = blockIdx.x;
    const int t = threadIdx.x;
    const int w = t >> 5, lane = t & 31;
    const uint32_t kvS  = smem_u32(kv);
    const uint32_t qtsS = smem_u32(qts);

    int mv = (lane < NN) ? (masks[(size_t)b * NN + lane] != 0) : 0;
    uint32_t mb = __ballot_sync(0xffffffffu, mv) & 0xFFFFFu;
    const bool allmask = (mb == 0);
    if (allmask) mb = 0xFFFFFu;
    const int nact = __popc(mb);

    for (int i = t; i < QT / 4; i += 320)
        cp16(qtsS + i * 16, g_qt + (size_t)b * NPAD1 + i * 4, true);
    for (int i = t; i < nact * (NODE_D / 4); i += 320) {
        int s = i / (NODE_D / 4), j4 = i % (NODE_D / 4);
        int n = __fns(mb, 0, s + 1);
        cp16(kvS + (s * KD + j4 * 4) * 4,
             nbr_node + ((size_t)b * NN + n) * NODE_D + j4 * 4, true);
    }
    for (int i = t; i < nact * (EDGE_D / 4); i += 320) {
        int s = i / (EDGE_D / 4), j4 = i % (EDGE_D / 4);
        int n = __fns(mb, 0, s + 1);
        cp16(kvS + (s * KD + NODE_D + j4 * 4) * 4,
             nbr_edge + ((size_t)b * NN + n) * EDGE_D + j4 * 4, true);
    }
    for (int i = t; i < nact * (TIME_D / 4); i += 320) {
        int s = i / (TIME_D / 4), j4 = i % (TIME_D / 4);
        int n = __fns(mb, 0, s + 1);
        cp16(kvS + (s * KD + NODE_D + EDGE_D + j4 * 4) * 4,
             nbr_time + ((size_t)b * NN + n) * TIME_D + j4 * 4, true);
    }
    if (t < NH * NN) sc[t] = -1e10f;
    CP_COMMIT();
    CP_WAIT(0);
    __syncthreads();

    // ---- scores: warp w -> slots w and w+10, both heads ----
#pragma unroll
    for (int rep = 0; rep < 2; rep++) {
        int s = w + rep * 10;
        if (s < nact) {
            int n = __fns(mb, 0, s + 1);
            float a0 = 0.f, a1 = 0.f;
            for (int j = lane; j < KD; j += 32) {
                float kvv = kv[s * KD + j];
                a0 += qts[j] * kvv;
                a1 += qts[KD + j] * kvv;
            }
#pragma unroll
            for (int o = 16; o; o >>= 1) {
                a0 += __shfl_xor_sync(0xffffffffu, a0, o);
                a1 += __shfl_xor_sync(0xffffffffu, a1, o);
            }
            if (lane == 0) {
                sc[n]      = allmask ? 0.f : a0 * ATTN_SCALE;
                sc[NN + n] = allmask ? 0.f : a1 * ATTN_SCALE;
            }
        }
    }
    __syncthreads();

    // ---- softmax: warp h handles head h; write attn output + slot weights ----
    if (w < NH) {
        const int h = w;
        float x = (lane < NN) ? sc[h * NN + lane] : -INFINITY;
        float m = x;
#pragma unroll
        for (int o = 16; o; o >>= 1) m = fmaxf(m, __shfl_xor_sync(0xffffffffu, m, o));
        float e = (lane < NN) ? __expf(x - m) : 0.f;
        float ssum = e;
#pragma unroll
        for (int o = 16; o; o >>= 1) ssum += __shfl_xor_sync(0xffffffffu, ssum, o);
        float a = e / ssum;
        if (lane < NN) {
            out[(size_t)BB * QD + ((size_t)b * NH + h) * NN + lane] = a;
            if ((mb >> lane) & 1u) {
                int s = __popc(mb & ((1u << lane) - 1u));
                aw[h * NN + s] = a;
            }
        }
    }
    __syncthreads();

    // ---- ctx: sum over ACTIVE slots, both heads per element ----
    for (int j = t; j < KD; j += 320) {
        float c0 = 0.f, c1 = 0.f;
        for (int s = 0; s < nact; ++s) {
            float kvv = kv[s * KD + j];
            c0 += aw[s] * kvv;
            c1 += aw[NN + s] * kvv;
        }
        __nv_bfloat16 h0 = __float2bfloat16(c0);
        __nv_bfloat16 h1 = __float2bfloat16(c1);
        size_t base = (size_t)b * KPAD2;
        g_cxh[base + j]      = h0;
        g_cxl[base + j]      = __float2bfloat16(c0 - __bfloat162float(h0));
        g_cxh[base + KD + j] = h1;
        g_cxl[base + KD + j] = __float2bfloat16(c1 - __bfloat162float(h1));
    }
    if (t < KPAD2 - QT) {
        g_cxh[(size_t)b * KPAD2 + QT + t] = __float2bfloat16(0.f);
        g_cxl[(size_t)b * KPAD2 + QT + t] = __float2bfloat16(0.f);
    }
}

// ---------------- LayerNorm, one warp per row ---------------------------------
__global__ __launch_bounds__(256)
void k_ln(const float* __restrict__ gamma, const float* __restrict__ beta,
          float* __restrict__ out)
{
    int gw   = (blockIdx.x * blockDim.x + threadIdx.x) >> 5;
    int lane = threadIdx.x & 31;
    if (gw >= BB) return;
    const float* x = g_x + (size_t)gw * QD;
    float s = 0.f, s2 = 0.f;
    for (int j = lane; j < QD; j += 32) { float v = x[j]; s += v; s2 += v * v; }
#pragma unroll
    for (int o = 16; o; o >>= 1) {
        s  += __shfl_xor_sync(0xffffffffu, s,  o);
        s2 += __shfl_xor_sync(0xffffffffu, s2, o);
    }
    float mu   = s * (1.f / QD);
    float var  = s2 * (1.f / QD) - mu * mu;
    float rstd = rsqrtf(var + LN_EPS);
    for (int j = lane; j < QD; j += 32)
        out[(size_t)gw * QD + j] = (x[j] - mu) * rstd * gamma[j] + beta[j];
}

// ---------------- side stream for weight folds (created once, outside capture)
struct SideRes {
    cudaStream_t s1;
    cudaEvent_t root, eFM, eFRV;
    SideRes() {
        cudaStreamCreateWithFlags(&s1, cudaStreamNonBlocking);
        cudaEventCreateWithFlags(&root, cudaEventDisableTiming);
        cudaEventCreateWithFlags(&eFM,  cudaEventDisableTiming);
        cudaEventCreateWithFlags(&eFRV, cudaEventDisableTiming);
    }
};
static SideRes g_side;

// ---------------- launch ------------------------------------------------------
#define SMEM1 (2 * (4 * 128 * 2 * RSTR))                       // 81920 (2-stage, BN=128)
#define SMEM2 (3 * (2 * 128 * 2 * RSTR + 2 * 96 * 2 * RSTR))   // 107520 (3-stage, BN=96)

extern "C" void kernel_launch(void* const* d_in, const int* in_sizes, int n_in,
                              void* d_out, int out_size)
{
    const float* nodef    = (const float*)d_in[0];
    const float* ntime    = (const float*)d_in[1];
    const float* nbr_node = (const float*)d_in[2];
    const float* nbr_time = (const float*)d_in[3];
    const float* nbr_edge = (const float*)d_in[4];
    const int*   masks    = (const int*)  d_in[5];
    const float* Wq       = (const float*)d_in[6];
    const float* Wk       = (const float*)d_in[7];
    const float* Wv       = (const float*)d_in[8];
    const float* Wr       = (const float*)d_in[9];
    const float* br       = (const float*)d_in[10];
    const float* gamma    = (const float*)d_in[11];
    const float* beta     = (const float*)d_in[12];
    float* out = (float*)d_out;

    auto g1 = k_gemm_mma<128, NCHUNK1, KPAD1, NPAD1, false, 1, 2, 1>;
    auto g2 = k_gemm_mma<96,  NCHUNK2, KPAD2, QD,    true,  2, 3, 2>;
    cudaFuncSetAttribute(g1, cudaFuncAttributeMaxDynamicSharedMemorySize, SMEM1);
    cudaFuncSetAttribute(g2, cudaFuncAttributeMaxDynamicSharedMemorySize, SMEM2);

    // weight folds on a side stream — overlap with prep_qin
    cudaEventRecord(g_side.root, 0);
    cudaStreamWaitEvent(g_side.s1, g_side.root, 0);
    k_fold_M <<<(NPAD1 * KPAD1 + 255) / 256, 256, 0, g_side.s1>>>(Wq, Wk);
    cudaEventRecord(g_side.eFM, g_side.s1);
    k_fold_Rv<<<(NPAD2 * KPAD2 + 255) / 256, 256, 0, g_side.s1>>>(Wr, Wv);
    cudaEventRecord(g_side.eFRV, g_side.s1);

    // main stream
    k_prep_qin<<<(BB * (KPAD1 / 4) + 255) / 256, 256>>>(nodef, ntime);

    cudaStreamWaitEvent(0, g_side.eFM, 0);
    dim3 grid1((BB + 127) / 128, NPAD1 / 128);
    g1<<<grid1, 256, SMEM1>>>(nodef, ntime, br);

    k_attn<<<BB, 320>>>(nbr_node, nbr_time, nbr_edge, masks, out);

    cudaStreamWaitEvent(0, g_side.eFRV, 0);
    dim3 grid2((BB + 127) / 128, NPAD2 / 96);
    g2<<<grid2, 256, SMEM2>>>(nodef, ntime, br);

    k_ln<<<(BB * 32 + 255) / 256, 256>>>(gamma, beta, out);
}

// round 14
// speedup vs baseline: 1.7710x; 1.0235x over previous
#include <cuda_runtime.h>
#include <cuda_bf16.h>
#include <cstdint>

#define BB      20000
#define NN      20
#define NODE_D  172
#define EDGE_D  172
#define TIME_D  100
#define QD      272          // NODE_D + TIME_D
#define KD      444          // NODE_D + EDGE_D + TIME_D
#define NH      2
#define HD      136
#define QT      (NH*KD)      // 888
#define ATTN_SCALE 0.08574929257125442f   // 136^-0.5
#define LN_EPS  1e-5f

// GEMM geometry (K-chunk = 32 bf16)
#define KPAD1   288          // GEMM1 K (272 -> 9 chunks; last chunk half-real)
#define NPAD1   896          // GEMM1 N (888 -> 7 tiles of 128)
#define KPAD2   896          // GEMM2 K (888 -> 28 chunks)
#define NPAD2   288          // GEMM2 N (272 -> 3 tiles of 96)
#define NCHUNK1 9
#define NCHUNK2 28
#define RSTR    40           // smem row stride in bf16 (80 B)

// prelude partition
#define NB_PREP ((BB * (KPAD1 / 4) + 255) / 256)     // 5625
#define NB_FM   ((NPAD1 * KPAD1 + 255) / 256)        // 1008
#define NB_RV   ((NPAD2 * KPAD2 + 255) / 256)        // 1008

#define ATH     384          // attention threads (12 warps)

// ---------------- scratch -----------------------------------------------------
__device__ __align__(16) __nv_bfloat16 g_qin_hi[(size_t)BB * KPAD1];
__device__ __align__(16) __nv_bfloat16 g_qin_lo[(size_t)BB * KPAD1];
__device__ __align__(16) __nv_bfloat16 g_Mhi[NPAD1 * KPAD1];
__device__ __align__(16) __nv_bfloat16 g_Mlo[NPAD1 * KPAD1];
__device__ __align__(16) __nv_bfloat16 g_Rvhi[NPAD2 * KPAD2];
__device__ __align__(16) __nv_bfloat16 g_Rvlo[NPAD2 * KPAD2];
__device__ __align__(16) float         g_qt[(size_t)BB * NPAD1];
__device__ __align__(16) __nv_bfloat16 g_cxh[(size_t)BB * KPAD2];
__device__ __align__(16) __nv_bfloat16 g_cxl[(size_t)BB * KPAD2];
__device__ __align__(16) float         g_x[(size_t)BB * QD];

// ---------------- helpers -----------------------------------------------------
__device__ __forceinline__ uint32_t smem_u32(const void* p) {
    uint32_t a;
    asm("{ .reg .u64 t; cvta.to.shared.u64 t, %1; cvt.u32.u64 %0, t; }" : "=r"(a) : "l"(p));
    return a;
}
__device__ __forceinline__ void cp16(uint32_t dst, const void* src, bool v) {
    int sz = v ? 16 : 0;
    asm volatile("cp.async.cg.shared.global [%0], [%1], 16, %2;"
                 :: "r"(dst), "l"(src), "r"(sz));
}
#define CP_COMMIT() asm volatile("cp.async.commit_group;" ::: "memory")
#define CP_WAIT(n)  asm volatile("cp.async.wait_group %0;" :: "n"(n) : "memory")

#define LDM_X4(r, a) \
    asm volatile("ldmatrix.sync.aligned.m8n8.x4.shared.b16 {%0,%1,%2,%3}, [%4];" \
                 : "=r"((r)[0]), "=r"((r)[1]), "=r"((r)[2]), "=r"((r)[3]) : "r"(a))

__device__ __forceinline__ void mma_bf16(float* c, const uint32_t a[4],
                                         uint32_t b0, uint32_t b1) {
    asm volatile(
        "mma.sync.aligned.m16n8k16.row.col.f32.bf16.bf16.f32 "
        "{%0,%1,%2,%3}, {%4,%5,%6,%7}, {%8,%9}, {%0,%1,%2,%3};"
        : "+f"(c[0]), "+f"(c[1]), "+f"(c[2]), "+f"(c[3])
        : "r"(a[0]), "r"(a[1]), "r"(a[2]), "r"(a[3]), "r"(b0), "r"(b1));
}

__device__ __forceinline__ void split_bf16(float x, __nv_bfloat16& h, __nv_bfloat16& l) {
    h = __float2bfloat16(x);
    l = __float2bfloat16(x - __bfloat162float(h));
}

// ---------------- fused prelude: prep_qin | fold_M | fold_Rv ------------------
__global__ void k_prelude(const float* __restrict__ nodef, const float* __restrict__ ntime,
                          const float* __restrict__ Wq, const float* __restrict__ Wk,
                          const float* __restrict__ Wr, const float* __restrict__ Wv)
{
    const int bid = blockIdx.x;
    if (bid < NB_PREP) {
        // prep_qin: float4 in, two packed 8-byte stores out
        int i = bid * 256 + threadIdx.x;
        if (i >= BB * (KPAD1 / 4)) return;
        int r = i / (KPAD1 / 4), c = (i % (KPAD1 / 4)) * 4;
        float4 x = make_float4(0.f, 0.f, 0.f, 0.f);
        if (c < NODE_D)   x = *(const float4*)(nodef + (size_t)r * NODE_D + c);
        else if (c < QD)  x = *(const float4*)(ntime + (size_t)r * TIME_D + (c - NODE_D));
        uint64_t ph, pl;
        __nv_bfloat16* hh = (__nv_bfloat16*)&ph;
        __nv_bfloat16* ll = (__nv_bfloat16*)&pl;
        split_bf16(x.x, hh[0], ll[0]);
        split_bf16(x.y, hh[1], ll[1]);
        split_bf16(x.z, hh[2], ll[2]);
        split_bf16(x.w, hh[3], ll[3]);
        *(uint64_t*)(g_qin_hi + (size_t)i * 4) = ph;
        *(uint64_t*)(g_qin_lo + (size_t)i * 4) = pl;
    } else if (bid < NB_PREP + NB_FM) {
        // fold M = Wk^T Wq per head -> hi/lo [896, 288]
        int tid = (bid - NB_PREP) * 256 + threadIdx.x;
        if (tid >= NPAD1 * KPAD1) return;
        int c = tid % KPAD1;
        int o = tid / KPAD1;
        float acc = 0.f;
        if (o < QT && c < QD) {
            int h = o / KD, j = o % KD;
            const float* wk = Wk + (size_t)(h * HD) * KD + j;
            const float* wq = Wq + (size_t)(h * HD) * QD + c;
#pragma unroll 8
            for (int d = 0; d < HD; ++d)
                acc += wk[(size_t)d * KD] * wq[(size_t)d * QD];
        }
        __nv_bfloat16 h16, l16; split_bf16(acc, h16, l16);
        g_Mhi[tid] = h16; g_Mlo[tid] = l16;
    } else {
        // fold Rv = Wr Wv per head -> hi/lo [288, 896]
        int tid = (bid - NB_PREP - NB_FM) * 256 + threadIdx.x;
        if (tid >= NPAD2 * KPAD2) return;
        int p = tid % KPAD2;
        int o = tid / KPAD2;
        float acc = 0.f;
        if (o < QD && p < QT) {
            int h = p / KD, j = p % KD;
            const float* wr = Wr + (size_t)o * QD + h * HD;
            const float* wv = Wv + (size_t)(h * HD) * KD + j;
#pragma unroll 8
            for (int d = 0; d < HD; ++d)
                acc += wr[d] * wv[(size_t)d * KD];
        }
        __nv_bfloat16 h16, l16; split_bf16(acc, h16, l16);
        g_Rvhi[tid] = h16; g_Rvlo[tid] = l16;
    }
}

// ---------------- bf16x3 HMMA GEMM --------------------------------------------
// HALFLAST: if true, the last k-chunk computes only its lower 16 columns
// (upper 16 are zero padding -> exact no-ops). Implemented by statically
// peeling the final chunk; no dynamic control flow inside unrolled loops.
template<int BN, int NCH, int KP, int OSTR, bool FUSE, int WHICH, int STAGES, bool HALFLAST>
__global__ __launch_bounds__(256)
void k_gemm_mma(const float* __restrict__ nodef, const float* __restrict__ ntime,
                const float* __restrict__ br)
{
    const __nv_bfloat16* __restrict__ Ah = (WHICH == 1) ? g_qin_hi : g_cxh;
    const __nv_bfloat16* __restrict__ Al = (WHICH == 1) ? g_qin_lo : g_cxl;
    const __nv_bfloat16* __restrict__ Bh = (WHICH == 1) ? g_Mhi : g_Rvhi;
    const __nv_bfloat16* __restrict__ Bl = (WHICH == 1) ? g_Mlo : g_Rvlo;
    float* __restrict__ outp             = (WHICH == 1) ? g_qt : g_x;

    constexpr int WN   = BN / 2;
    constexpr int WNS  = WN / 8;
    constexpr int NG   = WN / 16;
    constexpr int OFF_AL = 128 * 2 * RSTR;
    constexpr int OFF_BH = 2 * OFF_AL;
    constexpr int OFF_BL = OFF_BH + BN * 2 * RSTR;
    constexpr int STRIDE = OFF_BL + BN * 2 * RSTR;

    extern __shared__ char sm[];
    const uint32_t S = smem_u32(sm);
    const int t = threadIdx.x, lane = t & 31, wid = t >> 5;
    const int warpM = wid & 3, warpN = wid >> 2;
    const int bm = blockIdx.x, bn = blockIdx.y;

    float acc[2][WNS][4];
#pragma unroll
    for (int i = 0; i < 2; i++)
#pragma unroll
        for (int j = 0; j < WNS; j++)
#pragma unroll
            for (int q = 0; q < 4; q++) acc[i][j][q] = 0.f;

    auto load_chunk = [&](int c, int b) {
        const uint32_t base = S + b * STRIDE;
        for (int i = t; i < 512; i += 256) {
            int row = i >> 2, seg = i & 3;
            int gr = bm * 128 + row;
            bool v = gr < BB;
            int grc = v ? gr : (BB - 1);
            size_t off = (size_t)grc * KP + c * 32 + seg * 8;
            cp16(base + row * 80 + seg * 16, Ah + off, v);
            cp16(base + OFF_AL + row * 80 + seg * 16, Al + off, v);
        }
        for (int i = t; i < BN * 4; i += 256) {
            int row = i >> 2, seg = i & 3;
            size_t off = (size_t)(bn * BN + row) * KP + c * 32 + seg * 8;
            cp16(base + OFF_BH + row * 80 + seg * 16, Bh + off, true);
            cp16(base + OFF_BL + row * 80 + seg * 16, Bl + off, true);
        }
    };

    // one 16-wide k-half of compute, fully unrolled
    auto compute_half = [&](uint32_t base, int kk) {
        const uint32_t lrow = lane & 15;
        const uint32_t lcol = (lane >> 4) * 16;
        const uint32_t kb = kk * 32 + lcol;
        uint32_t a_hi[2][4], a_lo[2][4];
#pragma unroll
        for (int ms = 0; ms < 2; ms++) {
            uint32_t r0 = (warpM * 32 + ms * 16 + lrow) * 80 + kb;
            LDM_X4(a_hi[ms], base + r0);
            LDM_X4(a_lo[ms], base + OFF_AL + r0);
        }
#pragma unroll
        for (int ng = 0; ng < NG; ng++) {
            uint32_t bh[4], bl[4];
            uint32_t r0 = (warpN * WN + ng * 16 + lrow) * 80 + kb;
            LDM_X4(bh, base + OFF_BH + r0);
            LDM_X4(bl, base + OFF_BL + r0);
#pragma unroll
            for (int ms = 0; ms < 2; ms++) {
                mma_bf16(acc[ms][2*ng],   a_hi[ms], bh[0], bh[2]);
                mma_bf16(acc[ms][2*ng+1], a_hi[ms], bh[1], bh[3]);
            }
#pragma unroll
            for (int ms = 0; ms < 2; ms++) {
                mma_bf16(acc[ms][2*ng],   a_hi[ms], bl[0], bl[2]);
                mma_bf16(acc[ms][2*ng+1], a_hi[ms], bl[1], bl[3]);
            }
#pragma unroll
            for (int ms = 0; ms < 2; ms++) {
                mma_bf16(acc[ms][2*ng],   a_lo[ms], bh[0], bh[2]);
                mma_bf16(acc[ms][2*ng+1], a_lo[ms], bh[1], bh[3]);
            }
        }
    };

    if (STAGES == 2) {
        load_chunk(0, 0); CP_COMMIT();
        // all chunks except the last: full compute
        for (int c = 0; c < NCH - 1; c++) {
            load_chunk(c + 1, (c + 1) & 1); CP_COMMIT(); CP_WAIT(1);
            __syncthreads();
            compute_half(S + (c & 1) * STRIDE, 0);
            compute_half(S + (c & 1) * STRIDE, 1);
            __syncthreads();
        }
        // last chunk, statically half or full
        CP_WAIT(0);
        __syncthreads();
        {
            const uint32_t base = S + ((NCH - 1) & 1) * STRIDE;
            compute_half(base, 0);
            if (!HALFLAST) compute_half(base, 1);
        }
    } else {
        load_chunk(0, 0); CP_COMMIT();
        load_chunk(1, 1); CP_COMMIT();
        int bufc = 0;
        for (int c = 0; c < NCH; c++) {
            CP_WAIT(1);
            __syncthreads();
            if (c + 2 < NCH) {
                int b2 = bufc + 2; if (b2 >= 3) b2 -= 3;
                load_chunk(c + 2, b2);
            }
            CP_COMMIT();
            const uint32_t base = S + bufc * STRIDE;
            compute_half(base, 0);
            compute_half(base, 1);
            bufc = (bufc == 2) ? 0 : bufc + 1;
        }
    }

    const int g = lane >> 2, tq = lane & 3;
#pragma unroll
    for (int ms = 0; ms < 2; ms++) {
#pragma unroll
        for (int ns = 0; ns < WNS; ns++) {
            int row = bm * 128 + warpM * 32 + ms * 16 + g;
            int col = bn * BN + warpN * WN + ns * 8 + tq * 2;
#pragma unroll
            for (int half = 0; half < 2; half++) {
                int r = row + half * 8;
                if (r >= BB) continue;
                float v0 = acc[ms][ns][half * 2 + 0];
                float v1 = acc[ms][ns][half * 2 + 1];
                if (FUSE) {
                    if (col >= QD) continue;
                    float2 res;
                    if (col < NODE_D) res = *(const float2*)(nodef + (size_t)r * NODE_D + col);
                    else              res = *(const float2*)(ntime + (size_t)r * TIME_D + (col - NODE_D));
                    float2 bb = *(const float2*)(br + col);
                    v0 += bb.x + res.x;
                    v1 += bb.y + res.y;
                }
                *(float2*)(outp + (size_t)r * OSTR + col) = make_float2(v0, v1);
            }
        }
    }
}

// ---------------- K2: mask-compacted streaming attention (384 threads) --------
__global__ __launch_bounds__(ATH)
void k_attn(const float* __restrict__ nbr_node, const float* __restrict__ nbr_time,
            const float* __restrict__ nbr_edge, const int* __restrict__ masks,
            float* __restrict__ out)
{
    __shared__ __align__(16) float kv[NN * KD];   // compact slots
    __shared__ __align__(16) float qts[QT];
    __shared__ float sc[NH * NN];                 // scores/attn by neighbor idx
    __shared__ float aw[NH * NN];                 // attn by compact slot

    const int b = blockIdx.x;
    const int t = threadIdx.x;
    const int w = t >> 5, lane = t & 31;
    const uint32_t kvS  = smem_u32(kv);
    const uint32_t qtsS = smem_u32(qts);

    int mv = (lane < NN) ? (masks[(size_t)b * NN + lane] != 0) : 0;
    uint32_t mb = __ballot_sync(0xffffffffu, mv) & 0xFFFFFu;
    const bool allmask = (mb == 0);
    if (allmask) mb = 0xFFFFFu;
    const int nact = __popc(mb);

    for (int i = t; i < QT / 4; i += ATH)
        cp16(qtsS + i * 16, g_qt + (size_t)b * NPAD1 + i * 4, true);
    for (int i = t; i < nact * (NODE_D / 4); i += ATH) {
        int s = i / (NODE_D / 4), j4 = i % (NODE_D / 4);
        int n = __fns(mb, 0, s + 1);
        cp16(kvS + (s * KD + j4 * 4) * 4,
             nbr_node + ((size_t)b * NN + n) * NODE_D + j4 * 4, true);
    }
    for (int i = t; i < nact * (EDGE_D / 4); i += ATH) {
        int s = i / (EDGE_D / 4), j4 = i % (EDGE_D / 4);
        int n = __fns(mb, 0, s + 1);
        cp16(kvS + (s * KD + NODE_D + j4 * 4) * 4,
             nbr_edge + ((size_t)b * NN + n) * EDGE_D + j4 * 4, true);
    }
    for (int i = t; i < nact * (TIME_D / 4); i += ATH) {
        int s = i / (TIME_D / 4), j4 = i % (TIME_D / 4);
        int n = __fns(mb, 0, s + 1);
        cp16(kvS + (s * KD + NODE_D + EDGE_D + j4 * 4) * 4,
             nbr_time + ((size_t)b * NN + n) * TIME_D + j4 * 4, true);
    }
    if (t < NH * NN) sc[t] = -1e10f;
    CP_COMMIT();
    CP_WAIT(0);
    __syncthreads();

    // ---- scores: warp w -> slots w and w+12, both heads ----
#pragma unroll
    for (int rep = 0; rep < 2; rep++) {
        int s = w + rep * 12;
        if (s < nact) {
            int n = __fns(mb, 0, s + 1);
            float a0 = 0.f, a1 = 0.f;
            for (int j = lane; j < KD; j += 32) {
                float kvv = kv[s * KD + j];
                a0 += qts[j] * kvv;
                a1 += qts[KD + j] * kvv;
            }
#pragma unroll
            for (int o = 16; o; o >>= 1) {
                a0 += __shfl_xor_sync(0xffffffffu, a0, o);
                a1 += __shfl_xor_sync(0xffffffffu, a1, o);
            }
            if (lane == 0) {
                sc[n]      = allmask ? 0.f : a0 * ATTN_SCALE;
                sc[NN + n] = allmask ? 0.f : a1 * ATTN_SCALE;
            }
        }
    }
    __syncthreads();

    // ---- softmax: warp h handles head h; write attn output + slot weights ----
    if (w < NH) {
        const int h = w;
        float x = (lane < NN) ? sc[h * NN + lane] : -INFINITY;
        float m = x;
#pragma unroll
        for (int o = 16; o; o >>= 1) m = fmaxf(m, __shfl_xor_sync(0xffffffffu, m, o));
        float e = (lane < NN) ? __expf(x - m) : 0.f;
        float ssum = e;
#pragma unroll
        for (int o = 16; o; o >>= 1) ssum += __shfl_xor_sync(0xffffffffu, ssum, o);
        float a = e / ssum;
        if (lane < NN) {
            out[(size_t)BB * QD + ((size_t)b * NH + h) * NN + lane] = a;
            if ((mb >> lane) & 1u) {
                int s = __popc(mb & ((1u << lane) - 1u));
                aw[h * NN + s] = a;
            }
        }
    }
    __syncthreads();

    // ---- ctx: sum over ACTIVE slots, both heads per element ----
    for (int j = t; j < KD; j += ATH) {
        float c0 = 0.f, c1 = 0.f;
        for (int s = 0; s < nact; ++s) {
            float kvv = kv[s * KD + j];
            c0 += aw[s] * kvv;
            c1 += aw[NN + s] * kvv;
        }
        __nv_bfloat16 h0 = __float2bfloat16(c0);
        __nv_bfloat16 h1 = __float2bfloat16(c1);
        size_t base = (size_t)b * KPAD2;
        g_cxh[base + j]      = h0;
        g_cxl[base + j]      = __float2bfloat16(c0 - __bfloat162float(h0));
        g_cxh[base + KD + j] = h1;
        g_cxl[base + KD + j] = __float2bfloat16(c1 - __bfloat162float(h1));
    }
    if (t < KPAD2 - QT) {
        g_cxh[(size_t)b * KPAD2 + QT + t] = __float2bfloat16(0.f);
        g_cxl[(size_t)b * KPAD2 + QT + t] = __float2bfloat16(0.f);
    }
}

// ---------------- LayerNorm, one warp per row ---------------------------------
__global__ __launch_bounds__(256)
void k_ln(const float* __restrict__ gamma, const float* __restrict__ beta,
          float* __restrict__ out)
{
    int gw   = (blockIdx.x * blockDim.x + threadIdx.x) >> 5;
    int lane = threadIdx.x & 31;
    if (gw >= BB) return;
    const float* x = g_x + (size_t)gw * QD;
    float s = 0.f, s2 = 0.f;
    for (int j = lane; j < QD; j += 32) { float v = x[j]; s += v; s2 += v * v; }
#pragma unroll
    for (int o = 16; o; o >>= 1) {
        s  += __shfl_xor_sync(0xffffffffu, s,  o);
        s2 += __shfl_xor_sync(0xffffffffu, s2, o);
    }
    float mu   = s * (1.f / QD);
    float var  = s2 * (1.f / QD) - mu * mu;
    float rstd = rsqrtf(var + LN_EPS);
    for (int j = lane; j < QD; j += 32)
        out[(size_t)gw * QD + j] = (x[j] - mu) * rstd * gamma[j] + beta[j];
}

// ---------------- launch ------------------------------------------------------
#define SMEM1 (2 * (4 * 128 * 2 * RSTR))                       // 81920 (2-stage, BN=128)
#define SMEM2 (3 * (2 * 128 * 2 * RSTR + 2 * 96 * 2 * RSTR))   // 107520 (3-stage, BN=96)

extern "C" void kernel_launch(void* const* d_in, const int* in_sizes, int n_in,
                              void* d_out, int out_size)
{
    const float* nodef    = (const float*)d_in[0];
    const float* ntime    = (const float*)d_in[1];
    const float* nbr_node = (const float*)d_in[2];
    const float* nbr_time = (const float*)d_in[3];
    const float* nbr_edge = (const float*)d_in[4];
    const int*   masks    = (const int*)  d_in[5];
    const float* Wq       = (const float*)d_in[6];
    const float* Wk       = (const float*)d_in[7];
    const float* Wv       = (const float*)d_in[8];
    const float* Wr       = (const float*)d_in[9];
    const float* br       = (const float*)d_in[10];
    const float* gamma    = (const float*)d_in[11];
    const float* beta     = (const float*)d_in[12];
    float* out = (float*)d_out;

    auto g1 = k_gemm_mma<128, NCHUNK1, KPAD1, NPAD1, false, 1, 2, true>;
    auto g2 = k_gemm_mma<96,  NCHUNK2, KPAD2, QD,    true,  2, 3, false>;
    cudaFuncSetAttribute(g1, cudaFuncAttributeMaxDynamicSharedMemorySize, SMEM1);
    cudaFuncSetAttribute(g2, cudaFuncAttributeMaxDynamicSharedMemorySize, SMEM2);

    k_prelude<<<NB_PREP + NB_FM + NB_RV, 256>>>(nodef, ntime, Wq, Wk, Wr, Wv);

    dim3 grid1((BB + 127) / 128, NPAD1 / 128);
    g1<<<grid1, 256, SMEM1>>>(nodef, ntime, br);

    k_attn<<<BB, ATH>>>(nbr_node, nbr_time, nbr_edge, masks, out);

    dim3 grid2((BB + 127) / 128, NPAD2 / 96);
    g2<<<grid2, 256, SMEM2>>>(nodef, ntime, br);

    k_ln<<<(BB * 32 + 255) / 256, 256>>>(gamma, beta, out);
}

// round 15
// speedup vs baseline: 1.7968x; 1.0146x over previous
#include <cuda_runtime.h>
#include <cuda_bf16.h>
#include <cstdint>

#define BB      20000
#define NN      20
#define NODE_D  172
#define EDGE_D  172
#define TIME_D  100
#define QD      272          // NODE_D + TIME_D
#define KD      444          // NODE_D + EDGE_D + TIME_D
#define NH      2
#define HD      136
#define QT      (NH*KD)      // 888
#define ATTN_SCALE 0.08574929257125442f   // 136^-0.5
#define LN_EPS  1e-5f

// GEMM geometry (K-chunk = 32 bf16)
#define KPAD1   288          // GEMM1 K (272 -> 9 chunks; last chunk half-real)
#define NPAD1   896          // GEMM1 N (888 -> 7 tiles of 128)
#define KPAD2   896          // GEMM2 K (888 -> 28 chunks)
#define NPAD2   288          // GEMM2 N (272 -> 3 tiles of 96)
#define NCHUNK1 9
#define NCHUNK2 28
#define RSTR    40           // smem row stride in bf16 (80 B)

// prelude partition
#define NB_PREP ((BB * (KPAD1 / 4) + 255) / 256)     // 5625
#define NB_FM   ((NPAD1 * KPAD1 + 255) / 256)        // 1008
#define NB_RV   ((NPAD2 * KPAD2 + 255) / 256)        // 1008

#define ATH     384          // attention threads (12 warps)

// ---------------- scratch -----------------------------------------------------
__device__ __align__(16) __nv_bfloat16 g_qin_hi[(size_t)BB * KPAD1];
__device__ __align__(16) __nv_bfloat16 g_qin_lo[(size_t)BB * KPAD1];
__device__ __align__(16) __nv_bfloat16 g_Mhi[NPAD1 * KPAD1];
__device__ __align__(16) __nv_bfloat16 g_Mlo[NPAD1 * KPAD1];
__device__ __align__(16) __nv_bfloat16 g_Rvhi[NPAD2 * KPAD2];
__device__ __align__(16) __nv_bfloat16 g_Rvlo[NPAD2 * KPAD2];
__device__ __align__(16) float         g_qt[(size_t)BB * NPAD1];
__device__ __align__(16) __nv_bfloat16 g_cxh[(size_t)BB * KPAD2];
__device__ __align__(16) __nv_bfloat16 g_cxl[(size_t)BB * KPAD2];
__device__ __align__(16) float         g_x[(size_t)BB * QD];

// ---------------- helpers -----------------------------------------------------
__device__ __forceinline__ uint32_t smem_u32(const void* p) {
    uint32_t a;
    asm("{ .reg .u64 t; cvta.to.shared.u64 t, %1; cvt.u32.u64 %0, t; }" : "=r"(a) : "l"(p));
    return a;
}
__device__ __forceinline__ void cp16(uint32_t dst, const void* src, bool v) {
    int sz = v ? 16 : 0;
    asm volatile("cp.async.cg.shared.global [%0], [%1], 16, %2;"
                 :: "r"(dst), "l"(src), "r"(sz));
}
#define CP_COMMIT() asm volatile("cp.async.commit_group;" ::: "memory")
#define CP_WAIT(n)  asm volatile("cp.async.wait_group %0;" :: "n"(n) : "memory")

#define LDM_X4(r, a) \
    asm volatile("ldmatrix.sync.aligned.m8n8.x4.shared.b16 {%0,%1,%2,%3}, [%4];" \
                 : "=r"((r)[0]), "=r"((r)[1]), "=r"((r)[2]), "=r"((r)[3]) : "r"(a))

__device__ __forceinline__ void mma_bf16(float* c, const uint32_t a[4],
                                         uint32_t b0, uint32_t b1) {
    asm volatile(
        "mma.sync.aligned.m16n8k16.row.col.f32.bf16.bf16.f32 "
        "{%0,%1,%2,%3}, {%4,%5,%6,%7}, {%8,%9}, {%0,%1,%2,%3};"
        : "+f"(c[0]), "+f"(c[1]), "+f"(c[2]), "+f"(c[3])
        : "r"(a[0]), "r"(a[1]), "r"(a[2]), "r"(a[3]), "r"(b0), "r"(b1));
}

__device__ __forceinline__ void split_bf16(float x, __nv_bfloat16& h, __nv_bfloat16& l) {
    h = __float2bfloat16(x);
    l = __float2bfloat16(x - __bfloat162float(h));
}

// ---------------- fused prelude: prep_qin | fold_M | fold_Rv ------------------
__global__ void k_prelude(const float* __restrict__ nodef, const float* __restrict__ ntime,
                          const float* __restrict__ Wq, const float* __restrict__ Wk,
                          const float* __restrict__ Wr, const float* __restrict__ Wv)
{
    const int bid = blockIdx.x;
    if (bid < NB_PREP) {
        int i = bid * 256 + threadIdx.x;
        if (i >= BB * (KPAD1 / 4)) return;
        int r = i / (KPAD1 / 4), c = (i % (KPAD1 / 4)) * 4;
        float4 x = make_float4(0.f, 0.f, 0.f, 0.f);
        if (c < NODE_D)   x = *(const float4*)(nodef + (size_t)r * NODE_D + c);
        else if (c < QD)  x = *(const float4*)(ntime + (size_t)r * TIME_D + (c - NODE_D));
        uint64_t ph, pl;
        __nv_bfloat16* hh = (__nv_bfloat16*)&ph;
        __nv_bfloat16* ll = (__nv_bfloat16*)&pl;
        split_bf16(x.x, hh[0], ll[0]);
        split_bf16(x.y, hh[1], ll[1]);
        split_bf16(x.z, hh[2], ll[2]);
        split_bf16(x.w, hh[3], ll[3]);
        *(uint64_t*)(g_qin_hi + (size_t)i * 4) = ph;
        *(uint64_t*)(g_qin_lo + (size_t)i * 4) = pl;
    } else if (bid < NB_PREP + NB_FM) {
        int tid = (bid - NB_PREP) * 256 + threadIdx.x;
        if (tid >= NPAD1 * KPAD1) return;
        int c = tid % KPAD1;
        int o = tid / KPAD1;
        float acc = 0.f;
        if (o < QT && c < QD) {
            int h = o / KD, j = o % KD;
            const float* wk = Wk + (size_t)(h * HD) * KD + j;
            const float* wq = Wq + (size_t)(h * HD) * QD + c;
#pragma unroll 8
            for (int d = 0; d < HD; ++d)
                acc += wk[(size_t)d * KD] * wq[(size_t)d * QD];
        }
        __nv_bfloat16 h16, l16; split_bf16(acc, h16, l16);
        g_Mhi[tid] = h16; g_Mlo[tid] = l16;
    } else {
        int tid = (bid - NB_PREP - NB_FM) * 256 + threadIdx.x;
        if (tid >= NPAD2 * KPAD2) return;
        int p = tid % KPAD2;
        int o = tid / KPAD2;
        float acc = 0.f;
        if (o < QD && p < QT) {
            int h = p / KD, j = p % KD;
            const float* wr = Wr + (size_t)o * QD + h * HD;
            const float* wv = Wv + (size_t)(h * HD) * KD + j;
#pragma unroll 8
            for (int d = 0; d < HD; ++d)
                acc += wr[d] * wv[(size_t)d * KD];
        }
        __nv_bfloat16 h16, l16; split_bf16(acc, h16, l16);
        g_Rvhi[tid] = h16; g_Rvlo[tid] = l16;
    }
}

// ---------------- bf16x3 HMMA GEMM --------------------------------------------
// compute_chunk: R12-measured codegen (single lambda, static unrolled kk loop).
// HALFLAST (G1 only): last chunk peeled, computes only kk=0 (upper 16 cols are
// zero padding -> exact no-ops skipped).
template<int BN, int NCH, int KP, int OSTR, bool FUSE, int WHICH, int STAGES, bool HALFLAST>
__global__ __launch_bounds__(256)
void k_gemm_mma(const float* __restrict__ nodef, const float* __restrict__ ntime,
                const float* __restrict__ br)
{
    const __nv_bfloat16* __restrict__ Ah = (WHICH == 1) ? g_qin_hi : g_cxh;
    const __nv_bfloat16* __restrict__ Al = (WHICH == 1) ? g_qin_lo : g_cxl;
    const __nv_bfloat16* __restrict__ Bh = (WHICH == 1) ? g_Mhi : g_Rvhi;
    const __nv_bfloat16* __restrict__ Bl = (WHICH == 1) ? g_Mlo : g_Rvlo;
    float* __restrict__ outp             = (WHICH == 1) ? g_qt : g_x;

    constexpr int WN   = BN / 2;
    constexpr int WNS  = WN / 8;
    constexpr int NG   = WN / 16;
    constexpr int OFF_AL = 128 * 2 * RSTR;
    constexpr int OFF_BH = 2 * OFF_AL;
    constexpr int OFF_BL = OFF_BH + BN * 2 * RSTR;
    constexpr int STRIDE = OFF_BL + BN * 2 * RSTR;

    extern __shared__ char sm[];
    const uint32_t S = smem_u32(sm);
    const int t = threadIdx.x, lane = t & 31, wid = t >> 5;
    const int warpM = wid & 3, warpN = wid >> 2;
    const int bm = blockIdx.x, bn = blockIdx.y;

    float acc[2][WNS][4];
#pragma unroll
    for (int i = 0; i < 2; i++)
#pragma unroll
        for (int j = 0; j < WNS; j++)
#pragma unroll
            for (int q = 0; q < 4; q++) acc[i][j][q] = 0.f;

    auto load_chunk = [&](int c, int b) {
        const uint32_t base = S + b * STRIDE;
        for (int i = t; i < 512; i += 256) {
            int row = i >> 2, seg = i & 3;
            int gr = bm * 128 + row;
            bool v = gr < BB;
            int grc = v ? gr : (BB - 1);
            size_t off = (size_t)grc * KP + c * 32 + seg * 8;
            cp16(base + row * 80 + seg * 16, Ah + off, v);
            cp16(base + OFF_AL + row * 80 + seg * 16, Al + off, v);
        }
        for (int i = t; i < BN * 4; i += 256) {
            int row = i >> 2, seg = i & 3;
            size_t off = (size_t)(bn * BN + row) * KP + c * 32 + seg * 8;
            cp16(base + OFF_BH + row * 80 + seg * 16, Bh + off, true);
            cp16(base + OFF_BL + row * 80 + seg * 16, Bl + off, true);
        }
    };

    // R12-style full-chunk compute: static unrolled kk loop inside one lambda
    auto compute_chunk = [&](int bufIdx) {
        const uint32_t base = S + bufIdx * STRIDE;
        const uint32_t lrow = lane & 15;
        const uint32_t lcol = (lane >> 4) * 16;
#pragma unroll
        for (int kk = 0; kk < 2; kk++) {
            const uint32_t kb = kk * 32 + lcol;
            uint32_t a_hi[2][4], a_lo[2][4];
#pragma unroll
            for (int ms = 0; ms < 2; ms++) {
                uint32_t r0 = (warpM * 32 + ms * 16 + lrow) * 80 + kb;
                LDM_X4(a_hi[ms], base + r0);
                LDM_X4(a_lo[ms], base + OFF_AL + r0);
            }
#pragma unroll
            for (int ng = 0; ng < NG; ng++) {
                uint32_t bh[4], bl[4];
                uint32_t r0 = (warpN * WN + ng * 16 + lrow) * 80 + kb;
                LDM_X4(bh, base + OFF_BH + r0);
                LDM_X4(bl, base + OFF_BL + r0);
#pragma unroll
                for (int ms = 0; ms < 2; ms++) {
                    mma_bf16(acc[ms][2*ng],   a_hi[ms], bh[0], bh[2]);
                    mma_bf16(acc[ms][2*ng+1], a_hi[ms], bh[1], bh[3]);
                }
#pragma unroll
                for (int ms = 0; ms < 2; ms++) {
                    mma_bf16(acc[ms][2*ng],   a_hi[ms], bl[0], bl[2]);
                    mma_bf16(acc[ms][2*ng+1], a_hi[ms], bl[1], bl[3]);
                }
#pragma unroll
                for (int ms = 0; ms < 2; ms++) {
                    mma_bf16(acc[ms][2*ng],   a_lo[ms], bh[0], bh[2]);
                    mma_bf16(acc[ms][2*ng+1], a_lo[ms], bh[1], bh[3]);
                }
            }
        }
    };

    // half-chunk compute (kk=0 only) — used ONLY for G1's peeled final chunk
    auto compute_half0 = [&](int bufIdx) {
        const uint32_t base = S + bufIdx * STRIDE;
        const uint32_t lrow = lane & 15;
        const uint32_t lcol = (lane >> 4) * 16;
        const uint32_t kb = lcol;
        uint32_t a_hi[2][4], a_lo[2][4];
#pragma unroll
        for (int ms = 0; ms < 2; ms++) {
            uint32_t r0 = (warpM * 32 + ms * 16 + lrow) * 80 + kb;
            LDM_X4(a_hi[ms], base + r0);
            LDM_X4(a_lo[ms], base + OFF_AL + r0);
        }
#pragma unroll
        for (int ng = 0; ng < NG; ng++) {
            uint32_t bh[4], bl[4];
            uint32_t r0 = (warpN * WN + ng * 16 + lrow) * 80 + kb;
            LDM_X4(bh, base + OFF_BH + r0);
            LDM_X4(bl, base + OFF_BL + r0);
#pragma unroll
            for (int ms = 0; ms < 2; ms++) {
                mma_bf16(acc[ms][2*ng],   a_hi[ms], bh[0], bh[2]);
                mma_bf16(acc[ms][2*ng+1], a_hi[ms], bh[1], bh[3]);
            }
#pragma unroll
            for (int ms = 0; ms < 2; ms++) {
                mma_bf16(acc[ms][2*ng],   a_hi[ms], bl[0], bl[2]);
                mma_bf16(acc[ms][2*ng+1], a_hi[ms], bl[1], bl[3]);
            }
#pragma unroll
            for (int ms = 0; ms < 2; ms++) {
                mma_bf16(acc[ms][2*ng],   a_lo[ms], bh[0], bh[2]);
                mma_bf16(acc[ms][2*ng+1], a_lo[ms], bh[1], bh[3]);
            }
        }
    };

    if (STAGES == 2) {
        load_chunk(0, 0); CP_COMMIT();
        for (int c = 0; c < NCH - 1; c++) {
            load_chunk(c + 1, (c + 1) & 1); CP_COMMIT(); CP_WAIT(1);
            __syncthreads();
            compute_chunk(c & 1);
            __syncthreads();
        }
        CP_WAIT(0);
        __syncthreads();
        if (HALFLAST) compute_half0((NCH - 1) & 1);
        else          compute_chunk((NCH - 1) & 1);
    } else {
        load_chunk(0, 0); CP_COMMIT();
        load_chunk(1, 1); CP_COMMIT();
        int bufc = 0;
        for (int c = 0; c < NCH; c++) {
            CP_WAIT(1);
            __syncthreads();
            if (c + 2 < NCH) {
                int b2 = bufc + 2; if (b2 >= 3) b2 -= 3;
                load_chunk(c + 2, b2);
            }
            CP_COMMIT();
            compute_chunk(bufc);
            bufc = (bufc == 2) ? 0 : bufc + 1;
        }
    }

    const int g = lane >> 2, tq = lane & 3;
#pragma unroll
    for (int ms = 0; ms < 2; ms++) {
#pragma unroll
        for (int ns = 0; ns < WNS; ns++) {
            int row = bm * 128 + warpM * 32 + ms * 16 + g;
            int col = bn * BN + warpN * WN + ns * 8 + tq * 2;
#pragma unroll
            for (int half = 0; half < 2; half++) {
                int r = row + half * 8;
                if (r >= BB) continue;
                float v0 = acc[ms][ns][half * 2 + 0];
                float v1 = acc[ms][ns][half * 2 + 1];
                if (FUSE) {
                    if (col >= QD) continue;
                    float2 res;
                    if (col < NODE_D) res = *(const float2*)(nodef + (size_t)r * NODE_D + col);
                    else              res = *(const float2*)(ntime + (size_t)r * TIME_D + (col - NODE_D));
                    float2 bb = *(const float2*)(br + col);
                    v0 += bb.x + res.x;
                    v1 += bb.y + res.y;
                }
                *(float2*)(outp + (size_t)r * OSTR + col) = make_float2(v0, v1);
            }
        }
    }
}

// ---------------- K2: mask-compacted streaming attention (384 threads) --------
__global__ __launch_bounds__(ATH)
void k_attn(const float* __restrict__ nbr_node, const float* __restrict__ nbr_time,
            const float* __restrict__ nbr_edge, const int* __restrict__ masks,
            float* __restrict__ out)
{
    __shared__ __align__(16) float kv[NN * KD];   // compact slots
    __shared__ __align__(16) float qts[QT];
    __shared__ float sc[NH * NN];                 // scores/attn by neighbor idx
    __shared__ float aw[NH * NN];                 // attn by compact slot

    const int b = blockIdx.x;
    const int t = threadIdx.x;
    const int w = t >> 5, lane = t & 31;
    const uint32_t kvS  = smem_u32(kv);
    const uint32_t qtsS = smem_u32(qts);

    int mv = (lane < NN) ? (masks[(size_t)b * NN + lane] != 0) : 0;
    uint32_t mb = __ballot_sync(0xffffffffu, mv) & 0xFFFFFu;
    const bool allmask = (mb == 0);
    if (allmask) mb = 0xFFFFFu;
    const int nact = __popc(mb);

    for (int i = t; i < QT / 4; i += ATH)
        cp16(qtsS + i * 16, g_qt + (size_t)b * NPAD1 + i * 4, true);
    for (int i = t; i < nact * (NODE_D / 4); i += ATH) {
        int s = i / (NODE_D / 4), j4 = i % (NODE_D / 4);
        int n = __fns(mb, 0, s + 1);
        cp16(kvS + (s * KD + j4 * 4) * 4,
             nbr_node + ((size_t)b * NN + n) * NODE_D + j4 * 4, true);
    }
    for (int i = t; i < nact * (EDGE_D / 4); i += ATH) {
        int s = i / (EDGE_D / 4), j4 = i % (EDGE_D / 4);
        int n = __fns(mb, 0, s + 1);
        cp16(kvS + (s * KD + NODE_D + j4 * 4) * 4,
             nbr_edge + ((size_t)b * NN + n) * EDGE_D + j4 * 4, true);
    }
    for (int i = t; i < nact * (TIME_D / 4); i += ATH) {
        int s = i / (TIME_D / 4), j4 = i % (TIME_D / 4);
        int n = __fns(mb, 0, s + 1);
        cp16(kvS + (s * KD + NODE_D + EDGE_D + j4 * 4) * 4,
             nbr_time + ((size_t)b * NN + n) * TIME_D + j4 * 4, true);
    }
    if (t < NH * NN) sc[t] = -1e10f;
    CP_COMMIT();
    CP_WAIT(0);
    __syncthreads();

    // ---- scores: warp w -> slots w and w+12, both heads ----
#pragma unroll
    for (int rep = 0; rep < 2; rep++) {
        int s = w + rep * 12;
        if (s < nact) {
            int n = __fns(mb, 0, s + 1);
            float a0 = 0.f, a1 = 0.f;
            for (int j = lane; j < KD; j += 32) {
                float kvv = kv[s * KD + j];
                a0 += qts[j] * kvv;
                a1 += qts[KD + j] * kvv;
            }
#pragma unroll
            for (int o = 16; o; o >>= 1) {
                a0 += __shfl_xor_sync(0xffffffffu, a0, o);
                a1 += __shfl_xor_sync(0xffffffffu, a1, o);
            }
            if (lane == 0) {
                sc[n]      = allmask ? 0.f : a0 * ATTN_SCALE;
                sc[NN + n] = allmask ? 0.f : a1 * ATTN_SCALE;
            }
        }
    }
    __syncthreads();

    // ---- softmax: warp h handles head h; write attn output + slot weights ----
    if (w < NH) {
        const int h = w;
        float x = (lane < NN) ? sc[h * NN + lane] : -INFINITY;
        float m = x;
#pragma unroll
        for (int o = 16; o; o >>= 1) m = fmaxf(m, __shfl_xor_sync(0xffffffffu, m, o));
        float e = (lane < NN) ? __expf(x - m) : 0.f;
        float ssum = e;
#pragma unroll
        for (int o = 16; o; o >>= 1) ssum += __shfl_xor_sync(0xffffffffu, ssum, o);
        float a = e / ssum;
        if (lane < NN) {
            out[(size_t)BB * QD + ((size_t)b * NH + h) * NN + lane] = a;
            if ((mb >> lane) & 1u) {
                int s = __popc(mb & ((1u << lane) - 1u));
                aw[h * NN + s] = a;
            }
        }
    }
    __syncthreads();

    // ---- ctx: sum over ACTIVE slots, both heads per element ----
    for (int j = t; j < KD; j += ATH) {
        float c0 = 0.f, c1 = 0.f;
        for (int s = 0; s < nact; ++s) {
            float kvv = kv[s * KD + j];
            c0 += aw[s] * kvv;
            c1 += aw[NN + s] * kvv;
        }
        __nv_bfloat16 h0 = __float2bfloat16(c0);
        __nv_bfloat16 h1 = __float2bfloat16(c1);
        size_t base = (size_t)b * KPAD2;
        g_cxh[base + j]      = h0;
        g_cxl[base + j]      = __float2bfloat16(c0 - __bfloat162float(h0));
        g_cxh[base + KD + j] = h1;
        g_cxl[base + KD + j] = __float2bfloat16(c1 - __bfloat162float(h1));
    }
    if (t < KPAD2 - QT) {
        g_cxh[(size_t)b * KPAD2 + QT + t] = __float2bfloat16(0.f);
        g_cxl[(size_t)b * KPAD2 + QT + t] = __float2bfloat16(0.f);
    }
}

// ---------------- LayerNorm, one warp per row, float4-vectorized ---------------
__global__ __launch_bounds__(256)
void k_ln(const float* __restrict__ gamma, const float* __restrict__ beta,
          float* __restrict__ out)
{
    int gw   = (blockIdx.x * blockDim.x + threadIdx.x) >> 5;
    int lane = threadIdx.x & 31;
    if (gw >= BB) return;
    const float4* x4 = (const float4*)(g_x + (size_t)gw * QD);
    float s = 0.f, s2 = 0.f;
    for (int j = lane; j < QD / 4; j += 32) {
        float4 v = x4[j];
        s  += v.x + v.y + v.z + v.w;
        s2 += v.x * v.x + v.y * v.y + v.z * v.z + v.w * v.w;
    }
#pragma unroll
    for (int o = 16; o; o >>= 1) {
        s  += __shfl_xor_sync(0xffffffffu, s,  o);
        s2 += __shfl_xor_sync(0xffffffffu, s2, o);
    }
    float mu   = s * (1.f / QD);
    float var  = s2 * (1.f / QD) - mu * mu;
    float rstd = rsqrtf(var + LN_EPS);
    float4* o4 = (float4*)(out + (size_t)gw * QD);
    const float4* g4 = (const float4*)gamma;
    const float4* b4 = (const float4*)beta;
    for (int j = lane; j < QD / 4; j += 32) {
        float4 v = x4[j], gg = g4[j], bb = b4[j];
        v.x = (v.x - mu) * rstd * gg.x + bb.x;
        v.y = (v.y - mu) * rstd * gg.y + bb.y;
        v.z = (v.z - mu) * rstd * gg.z + bb.z;
        v.w = (v.w - mu) * rstd * gg.w + bb.w;
        o4[j] = v;
    }
}

// ---------------- launch ------------------------------------------------------
#define SMEM1 (2 * (4 * 128 * 2 * RSTR))                       // 81920 (2-stage, BN=128)
#define SMEM2 (3 * (2 * 128 * 2 * RSTR + 2 * 96 * 2 * RSTR))   // 107520 (3-stage, BN=96)

extern "C" void kernel_launch(void* const* d_in, const int* in_sizes, int n_in,
                              void* d_out, int out_size)
{
    const float* nodef    = (const float*)d_in[0];
    const float* ntime    = (const float*)d_in[1];
    const float* nbr_node = (const float*)d_in[2];
    const float* nbr_time = (const float*)d_in[3];
    const float* nbr_edge = (const float*)d_in[4];
    const int*   masks    = (const int*)  d_in[5];
    const float* Wq       = (const float*)d_in[6];
    const float* Wk       = (const float*)d_in[7];
    const float* Wv       = (const float*)d_in[8];
    const float* Wr       = (const float*)d_in[9];
    const float* br       = (const float*)d_in[10];
    const float* gamma    = (const float*)d_in[11];
    const float* beta     = (const float*)d_in[12];
    float* out = (float*)d_out;

    auto g1 = k_gemm_mma<128, NCHUNK1, KPAD1, NPAD1, false, 1, 2, true>;
    auto g2 = k_gemm_mma<96,  NCHUNK2, KPAD2, QD,    true,  2, 3, false>;
    cudaFuncSetAttribute(g1, cudaFuncAttributeMaxDynamicSharedMemorySize, SMEM1);
    cudaFuncSetAttribute(g2, cudaFuncAttributeMaxDynamicSharedMemorySize, SMEM2);

    k_prelude<<<NB_PREP + NB_FM + NB_RV, 256>>>(nodef, ntime, Wq, Wk, Wr, Wv);

    dim3 grid1((BB + 127) / 128, NPAD1 / 128);
    g1<<<grid1, 256, SMEM1>>>(nodef, ntime, br);

    k_attn<<<BB, ATH>>>(nbr_node, nbr_time, nbr_edge, masks, out);

    dim3 grid2((BB + 127) / 128, NPAD2 / 96);
    g2<<<grid2, 256, SMEM2>>>(nodef, ntime, br);

    k_ln<<<(BB * 32 + 255) / 256, 256>>>(gamma, beta, out);
}